// round 5
// baseline (speedup 1.0000x reference)
#include <cuda_runtime.h>
#include <math.h>

#define B_   16
#define L_   8192
#define D_   64
#define R_   4
#define NB_  128     // n_buckets = chunks per (b,r)
#define BL_  64      // bucket length (chunk size)
#define KS   132     // shared row stride for kT / p_s (multiple of 4, avoids conflicts)

// ---------------- scratch (static device memory; no allocations) ----------------
__device__ __align__(16) float         g_att[(size_t)B_*R_*L_*D_];   // 134 MB: per-round attention, original order
__device__ __align__(16) float         g_lse[B_*R_*L_];              // per-round LSE, original order
__device__ __align__(16) int           g_spos[B_*R_*L_];             // sorted slot -> original position
__device__ __align__(16) unsigned char g_sbkt[B_*R_*L_];             // sorted slot -> bucket id
__device__ __align__(16) unsigned char g_bkt[B_*R_*L_];              // (b,r,l) -> bucket id
__device__ float g_m[B_*R_];
__device__ float g_z[B_*R_];

// =====================================================================
// K1: LSH hash. One thread per (b,l); random matrix normalized & tiled
// in shared (two halves of 128 columns, 32 KB). argmax over [x, -x]
// with first-occurrence semantics (strict >), matching jnp.argmax.
// =====================================================================
__global__ void __launch_bounds__(128) hash_kernel(const float* __restrict__ q,
                                                   const float* __restrict__ rmat) {
    __shared__ float rm_s[128 * 64];   // [col][d]
    const int tid = threadIdx.x;
    const int b   = blockIdx.y;
    const int l   = blockIdx.x * 128 + tid;

    // load + normalize query row (scale-invariant for argmax, but match ref numerics)
    float qn[64];
    float ss = 0.f;
    const float4* qrow = (const float4*)(q + ((size_t)b * L_ + l) * D_);
#pragma unroll
    for (int d4 = 0; d4 < 16; ++d4) {
        float4 t = qrow[d4];
        qn[d4*4+0] = t.x; qn[d4*4+1] = t.y; qn[d4*4+2] = t.z; qn[d4*4+3] = t.w;
        ss += t.x*t.x + t.y*t.y + t.z*t.z + t.w*t.w;
    }
    const float inq = 1.f / fmaxf(sqrtf(ss), 1e-12f);
#pragma unroll
    for (int d = 0; d < 64; ++d) qn[d] *= inq;

    float bestP[4], bestN[4];
    int   bpi[4],   bni[4];
#pragma unroll
    for (int r = 0; r < 4; ++r) { bestP[r] = -1e30f; bestN[r] = -1e30f; bpi[r] = 0; bni[r] = 0; }

    const float* rm_b = rmat + (size_t)b * D_ * R_ * 64;  // [d][c], c = r*64+n, row stride 256

#pragma unroll
    for (int half = 0; half < 2; ++half) {
        __syncthreads();
        // load 128 columns x 64 d (coalesced on global, conflicted STS is one-time)
        for (int i = tid; i < 128 * 64; i += 128) {
            int d  = i >> 7;
            int cl = i & 127;
            rm_s[cl * 64 + d] = rm_b[d * 256 + half * 128 + cl];
        }
        __syncthreads();
        // normalize column `tid` over d (l2norm with max(n, 1e-12))
        {
            float s2 = 0.f;
#pragma unroll 8
            for (int d = 0; d < 64; ++d) { float x = rm_s[tid * 64 + d]; s2 += x * x; }
            float inv = 1.f / fmaxf(sqrtf(s2), 1e-12f);
#pragma unroll 8
            for (int d = 0; d < 64; ++d) rm_s[tid * 64 + d] *= inv;
        }
        __syncthreads();
#pragma unroll
        for (int r_loc = 0; r_loc < 2; ++r_loc) {
            const int r = half * 2 + r_loc;
            for (int n = 0; n < 64; ++n) {
                const float4* col = (const float4*)(rm_s + (r_loc * 64 + n) * 64);
                float a0 = 0.f, a1 = 0.f, a2 = 0.f, a3 = 0.f;
#pragma unroll
                for (int d4 = 0; d4 < 16; ++d4) {
                    float4 m4 = col[d4];
                    a0 = fmaf(qn[d4*4+0], m4.x, a0);
                    a1 = fmaf(qn[d4*4+1], m4.y, a1);
                    a2 = fmaf(qn[d4*4+2], m4.z, a2);
                    a3 = fmaf(qn[d4*4+3], m4.w, a3);
                }
                float x = (a0 + a1) + (a2 + a3);
                if ( x > bestP[r]) { bestP[r] =  x; bpi[r] = n; }
                if (-x > bestN[r]) { bestN[r] = -x; bni[r] = n; }
            }
        }
    }
#pragma unroll
    for (int r = 0; r < 4; ++r) {
        // concat([x, -x]): negative block only wins on strict >
        int idx = (bestN[r] > bestP[r]) ? (64 + bni[r]) : bpi[r];
        g_bkt[((size_t)(b * R_ + r)) * L_ + l] = (unsigned char)idx;
    }
}

// =====================================================================
// K2: stable counting sort per (b,r). Keys = bucket*L + pos, all unique,
// so argsort == stable sort by bucket with position order preserved.
// =====================================================================
__global__ void __launch_bounds__(256) sort_kernel() {
    __shared__ unsigned char bkt_s[L_];
    __shared__ int hist[128];
    __shared__ int basec[128];
    __shared__ int warp_hist[8][128];

    const int tid = threadIdx.x;
    const int br  = blockIdx.x;
    const size_t off = (size_t)br * L_;

    // load bucket ids
    {
        const int4* src = (const int4*)(g_bkt + off);
        int4* dst = (int4*)bkt_s;
        for (int i = tid; i < L_ / 16; i += 256) dst[i] = src[i];
    }
    if (tid < 128) hist[tid] = 0;
    __syncthreads();
    for (int i = tid; i < L_; i += 256) atomicAdd(&hist[bkt_s[i]], 1);
    __syncthreads();
    if (tid == 0) {
        int a = 0;
        for (int c = 0; c < 128; ++c) { basec[c] = a; a += hist[c]; }
    }
    __syncthreads();

    const int lane = tid & 31, w = tid >> 5;
    for (int it = 0; it < L_ / 256; ++it) {
        const int idx = it * 256 + tid;
        const int vv  = bkt_s[idx];
        const unsigned mask = __match_any_sync(0xffffffffu, vv);
        const unsigned lt   = (lane == 0) ? 0u : (0xffffffffu >> (32 - lane));
        const int rank = __popc(mask & lt);
        for (int k = lane; k < 128; k += 32) warp_hist[w][k] = 0;
        __syncwarp();
        if ((mask & lt) == 0) warp_hist[w][vv] = __popc(mask);  // lowest lane of group
        __syncthreads();
        int pre = 0;
        for (int ww = 0; ww < w; ++ww) pre += warp_hist[ww][vv];
        const int dest = basec[vv] + pre + rank;
        g_spos[off + dest] = idx;
        g_sbkt[off + dest] = (unsigned char)vv;
        __syncthreads();
        if (tid < 128) {
            int t2 = 0;
#pragma unroll
            for (int ww = 0; ww < 8; ++ww) t2 += warp_hist[ww][tid];
            basec[tid] += t2;
        }
        __syncthreads();
    }
}

// =====================================================================
// K3: lookback attention per (b, r, chunk). 256 threads.
//   shared: kT [64][KS] keys/queries d-major (raw, reused as p_s),
//           v_s [128][64] values j-major, invn/pos/sh per key slot.
//   thread (i = tid>>2, jq = tid&3): 32 of 128 keys for query row i,
//   softmax across the 4 threads via shuffles, then p@v with the same
//   4 threads split over d.
// =====================================================================
__global__ void __launch_bounds__(256) attend_kernel(const float* __restrict__ q,
                                                     const float* __restrict__ v) {
    extern __shared__ float sm[];
    float* kT     = sm;                       // 64*KS floats (also p_s later)
    float* v_s    = sm + 64 * KS;             // 128*64
    float* invn_s = v_s + 128 * 64;           // 128
    int*   pos_s  = (int*)(invn_s + 128);     // 128
    int*   sh_s   = pos_s + 128;              // 128

    const int tid   = threadIdx.x;
    const int bx    = blockIdx.x;
    const int chunk = bx & (NB_ - 1);
    const int br    = bx >> 7;
    const int b     = br >> 2;
    const int prev  = (chunk + NB_ - 1) & (NB_ - 1);
    const size_t brL = (size_t)br * L_;

    // -------- gather 128 rows (prev chunk = keys 0..63, current = 64..127) -----
    {
        const int lane = tid & 31, w = tid >> 5;
        for (int jr = w; jr < 128; jr += 8) {
            const int slot = (jr < 64) ? prev * BL_ + jr : chunk * BL_ + (jr - 64);
            int pos = 0, bk = 0;
            if (lane == 0) { pos = g_spos[brL + slot]; bk = g_sbkt[brL + slot]; }
            pos = __shfl_sync(0xffffffffu, pos, 0);
            bk  = __shfl_sync(0xffffffffu, bk, 0);
            float ssq = 0.f;
            if (lane < 16) {
                float4 t = *((const float4*)(q + ((size_t)b * L_ + pos) * D_) + lane);
                kT[(lane*4+0)*KS + jr] = t.x;
                kT[(lane*4+1)*KS + jr] = t.y;
                kT[(lane*4+2)*KS + jr] = t.z;
                kT[(lane*4+3)*KS + jr] = t.w;
                ssq = t.x*t.x + t.y*t.y + t.z*t.z + t.w*t.w;
            } else {
                float4 t = *((const float4*)(v + ((size_t)b * L_ + pos) * D_) + (lane - 16));
                *(float4*)(v_s + jr * 64 + (lane - 16) * 4) = t;
            }
#pragma unroll
            for (int o = 16; o > 0; o >>= 1) ssq += __shfl_xor_sync(0xffffffffu, ssq, o);
            if (lane == 0) {
                invn_s[jr] = 1.f / fmaxf(sqrtf(ssq), 1e-12f);
                pos_s[jr]  = pos;
                sh_s[jr]   = bk;
            }
        }
    }
    __syncthreads();

    const int i  = tid >> 2;
    const int jq = tid & 3;
    const int my_sh  = sh_s[64 + i];
    const int my_pos = pos_s[64 + i];
    const float* qcol = kT + 64 + i;      // query d at qcol[d*KS] (raw rq)

    // -------- qk + masks ------------------------------------------------------
    float p[8][4];
#pragma unroll
    for (int g = 0; g < 8; ++g) {
        const int j0 = jq * 4 + g * 16;
        float a0 = 0.f, a1 = 0.f, a2 = 0.f, a3 = 0.f;
        const float4* kp = (const float4*)(kT + j0);
#pragma unroll 16
        for (int d = 0; d < 64; ++d) {
            const float  qd = qcol[d * KS];
            const float4 kv = kp[d * (KS / 4)];
            a0 = fmaf(qd, kv.x, a0);
            a1 = fmaf(qd, kv.y, a1);
            a2 = fmaf(qd, kv.z, a2);
            a3 = fmaf(qd, kv.w, a3);
        }
        float t0 = a0 * invn_s[j0+0] * 0.125f;
        float t1 = a1 * invn_s[j0+1] * 0.125f;
        float t2 = a2 * invn_s[j0+2] * 0.125f;
        float t3 = a3 * invn_s[j0+3] * 0.125f;
        if (my_sh  != sh_s [j0+0]) t0 = -1e9f;
        if (my_sh  != sh_s [j0+1]) t1 = -1e9f;
        if (my_sh  != sh_s [j0+2]) t2 = -1e9f;
        if (my_sh  != sh_s [j0+3]) t3 = -1e9f;
        if (my_pos == pos_s[j0+0]) t0 = -1e5f;
        if (my_pos == pos_s[j0+1]) t1 = -1e5f;
        if (my_pos == pos_s[j0+2]) t2 = -1e5f;
        if (my_pos == pos_s[j0+3]) t3 = -1e5f;
        p[g][0] = t0; p[g][1] = t1; p[g][2] = t2; p[g][3] = t3;
    }

    // -------- softmax over 128 keys (4-thread group per row) -----------------
    float m = -1e30f;
#pragma unroll
    for (int g = 0; g < 8; ++g) {
        m = fmaxf(m, fmaxf(fmaxf(p[g][0], p[g][1]), fmaxf(p[g][2], p[g][3])));
    }
    m = fmaxf(m, __shfl_xor_sync(0xffffffffu, m, 1));
    m = fmaxf(m, __shfl_xor_sync(0xffffffffu, m, 2));
    float s = 0.f;
#pragma unroll
    for (int g = 0; g < 8; ++g)
        s += expf(p[g][0]-m) + expf(p[g][1]-m) + expf(p[g][2]-m) + expf(p[g][3]-m);
    s += __shfl_xor_sync(0xffffffffu, s, 1);
    s += __shfl_xor_sync(0xffffffffu, s, 2);
    const float lse = m + logf(s);
#pragma unroll
    for (int g = 0; g < 8; ++g) {
        p[g][0] = expf(p[g][0] - lse);
        p[g][1] = expf(p[g][1] - lse);
        p[g][2] = expf(p[g][2] - lse);
        p[g][3] = expf(p[g][3] - lse);
    }

    // -------- stage p into shared (reuse kT region) ---------------------------
    __syncthreads();   // all kT reads done
    float* p_s = kT;
#pragma unroll
    for (int g = 0; g < 8; ++g)
        *(float4*)(p_s + i * KS + jq * 4 + g * 16) = make_float4(p[g][0], p[g][1], p[g][2], p[g][3]);
    __syncthreads();

    // -------- att = p @ v ; thread (i, dq) owns d = dq*4 + g*16 + e -----------
    const int dq = jq;
    float4 acc0 = make_float4(0,0,0,0), acc1 = acc0, acc2 = acc0, acc3 = acc0;
    const float* prow = p_s + i * KS;
#pragma unroll 4
    for (int j = 0; j < 128; ++j) {
        const float pv = prow[j];
        const float* vr = v_s + j * 64 + dq * 4;
        float4 v0 = *(const float4*)(vr);
        float4 v1 = *(const float4*)(vr + 16);
        float4 v2 = *(const float4*)(vr + 32);
        float4 v3 = *(const float4*)(vr + 48);
        acc0.x = fmaf(pv, v0.x, acc0.x); acc0.y = fmaf(pv, v0.y, acc0.y);
        acc0.z = fmaf(pv, v0.z, acc0.z); acc0.w = fmaf(pv, v0.w, acc0.w);
        acc1.x = fmaf(pv, v1.x, acc1.x); acc1.y = fmaf(pv, v1.y, acc1.y);
        acc1.z = fmaf(pv, v1.z, acc1.z); acc1.w = fmaf(pv, v1.w, acc1.w);
        acc2.x = fmaf(pv, v2.x, acc2.x); acc2.y = fmaf(pv, v2.y, acc2.y);
        acc2.z = fmaf(pv, v2.z, acc2.z); acc2.w = fmaf(pv, v2.w, acc2.w);
        acc3.x = fmaf(pv, v3.x, acc3.x); acc3.y = fmaf(pv, v3.y, acc3.y);
        acc3.z = fmaf(pv, v3.z, acc3.z); acc3.w = fmaf(pv, v3.w, acc3.w);
    }

    float* orow = g_att + (brL + (size_t)my_pos) * D_;   // scatter to original position
    *(float4*)(orow + dq * 4)      = acc0;
    *(float4*)(orow + dq * 4 + 16) = acc1;
    *(float4*)(orow + dq * 4 + 32) = acc2;
    *(float4*)(orow + dq * 4 + 48) = acc3;
    if (jq == 0) g_lse[brL + (size_t)my_pos] = lse;
}

// =====================================================================
// K4: per-(b,r) softmax normalizer over L: m = max lse, z = sum exp(lse-m)
// =====================================================================
__global__ void __launch_bounds__(256) lse_reduce_kernel() {
    __shared__ float red[256];
    const int br = blockIdx.x, tid = threadIdx.x;
    const size_t off = (size_t)br * L_;
    float m = -1e30f;
    for (int i = tid; i < L_; i += 256) m = fmaxf(m, g_lse[off + i]);
    red[tid] = m; __syncthreads();
    for (int s2 = 128; s2 > 0; s2 >>= 1) {
        if (tid < s2) red[tid] = fmaxf(red[tid], red[tid + s2]);
        __syncthreads();
    }
    const float mm = red[0];
    __syncthreads();
    float s = 0.f;
    for (int i = tid; i < L_; i += 256) s += expf(g_lse[off + i] - mm);
    red[tid] = s; __syncthreads();
    for (int s2 = 128; s2 > 0; s2 >>= 1) {
        if (tid < s2) red[tid] += red[tid + s2];
        __syncthreads();
    }
    if (tid == 0) { g_m[br] = mm; g_z[br] = red[0]; }
}

// =====================================================================
// K5: out[b,l,d] = sum_r att[b,r,l,d] * exp(lse[b,r,l]-m[b,r]) / z[b,r]
// =====================================================================
__global__ void __launch_bounds__(256) combine_kernel(float* __restrict__ out) {
    const int tid = threadIdx.x;
    const int gl  = blockIdx.x * 4 + (tid >> 6);   // global row in [0, B*L)
    const int d   = tid & 63;
    const int b   = gl >> 13;                       // L = 8192
    const int l   = gl & (L_ - 1);
    float acc = 0.f;
#pragma unroll
    for (int r = 0; r < 4; ++r) {
        const int br = b * 4 + r;
        const size_t row = (size_t)br * L_ + l;
        const float w = expf(g_lse[row] - g_m[br]) / g_z[br];
        acc = fmaf(g_att[row * D_ + d], w, acc);
    }
    out[(size_t)gl * D_ + d] = acc;
}

// =====================================================================
extern "C" void kernel_launch(void* const* d_in, const int* in_sizes, int n_in,
                              void* d_out, int out_size) {
    const float* q   = (const float*)d_in[0];
    const float* v   = (const float*)d_in[1];
    const float* rmt = (const float*)d_in[2];
    float* out = (float*)d_out;
    (void)in_sizes; (void)n_in; (void)out_size;

    const int att_smem = (64 * KS + 128 * 64 + 128) * (int)sizeof(float) + 256 * (int)sizeof(int);
    cudaFuncSetAttribute(attend_kernel, cudaFuncAttributeMaxDynamicSharedMemorySize, att_smem);

    hash_kernel<<<dim3(L_ / 128, B_), 128>>>(q, rmt);
    sort_kernel<<<B_ * R_, 256>>>();
    attend_kernel<<<B_ * R_ * NB_, 256, att_smem>>>(q, v);
    lse_reduce_kernel<<<B_ * R_, 256>>>();
    combine_kernel<<<B_ * L_ / 4, 256>>>(out);
}

// round 10
// speedup vs baseline: 1.0002x; 1.0002x over previous
#include <cuda_runtime.h>
#include <math.h>

#define B_   16
#define L_   8192
#define D_   64
#define R_   4
#define NB_  128     // n_buckets = chunks per (b,r)
#define BL_  64      // bucket length (chunk size)
#define KS   132     // shared row stride for kT / p_s (multiple of 4, avoids conflicts)

// ---------------- scratch (static device memory; no allocations) ----------------
__device__ __align__(16) float         g_att[(size_t)B_*R_*L_*D_];   // 134 MB: per-round attention, original order
__device__ __align__(16) float         g_lse[B_*R_*L_];              // per-round LSE, original order
__device__ __align__(16) int           g_spos[B_*R_*L_];             // sorted slot -> original position
__device__ __align__(16) unsigned char g_sbkt[B_*R_*L_];             // sorted slot -> bucket id
__device__ __align__(16) unsigned char g_bkt[B_*R_*L_];              // (b,r,l) -> bucket id
__device__ float g_m[B_*R_];
__device__ float g_z[B_*R_];

// =====================================================================
// K1: LSH hash. One thread per (b,l); random matrix normalized & tiled
// in shared (two halves of 128 columns, 32 KB). argmax over [x, -x]
// with first-occurrence semantics (strict >), matching jnp.argmax.
// =====================================================================
__global__ void __launch_bounds__(128) hash_kernel(const float* __restrict__ q,
                                                   const float* __restrict__ rmat) {
    __shared__ float rm_s[128 * 64];   // [col][d]
    const int tid = threadIdx.x;
    const int b   = blockIdx.y;
    const int l   = blockIdx.x * 128 + tid;

    // load + normalize query row (scale-invariant for argmax, but match ref numerics)
    float qn[64];
    float ss = 0.f;
    const float4* qrow = (const float4*)(q + ((size_t)b * L_ + l) * D_);
#pragma unroll
    for (int d4 = 0; d4 < 16; ++d4) {
        float4 t = qrow[d4];
        qn[d4*4+0] = t.x; qn[d4*4+1] = t.y; qn[d4*4+2] = t.z; qn[d4*4+3] = t.w;
        ss += t.x*t.x + t.y*t.y + t.z*t.z + t.w*t.w;
    }
    const float inq = 1.f / fmaxf(sqrtf(ss), 1e-12f);
#pragma unroll
    for (int d = 0; d < 64; ++d) qn[d] *= inq;

    float bestP[4], bestN[4];
    int   bpi[4],   bni[4];
#pragma unroll
    for (int r = 0; r < 4; ++r) { bestP[r] = -1e30f; bestN[r] = -1e30f; bpi[r] = 0; bni[r] = 0; }

    const float* rm_b = rmat + (size_t)b * D_ * R_ * 64;  // [d][c], c = r*64+n, row stride 256

#pragma unroll
    for (int half = 0; half < 2; ++half) {
        __syncthreads();
        // load 128 columns x 64 d (coalesced on global, conflicted STS is one-time)
        for (int i = tid; i < 128 * 64; i += 128) {
            int d  = i >> 7;
            int cl = i & 127;
            rm_s[cl * 64 + d] = rm_b[d * 256 + half * 128 + cl];
        }
        __syncthreads();
        // normalize column `tid` over d (l2norm with max(n, 1e-12))
        {
            float s2 = 0.f;
#pragma unroll 8
            for (int d = 0; d < 64; ++d) { float x = rm_s[tid * 64 + d]; s2 += x * x; }
            float inv = 1.f / fmaxf(sqrtf(s2), 1e-12f);
#pragma unroll 8
            for (int d = 0; d < 64; ++d) rm_s[tid * 64 + d] *= inv;
        }
        __syncthreads();
#pragma unroll
        for (int r_loc = 0; r_loc < 2; ++r_loc) {
            const int r = half * 2 + r_loc;
            for (int n = 0; n < 64; ++n) {
                const float4* col = (const float4*)(rm_s + (r_loc * 64 + n) * 64);
                float a0 = 0.f, a1 = 0.f, a2 = 0.f, a3 = 0.f;
#pragma unroll
                for (int d4 = 0; d4 < 16; ++d4) {
                    float4 m4 = col[d4];
                    a0 = fmaf(qn[d4*4+0], m4.x, a0);
                    a1 = fmaf(qn[d4*4+1], m4.y, a1);
                    a2 = fmaf(qn[d4*4+2], m4.z, a2);
                    a3 = fmaf(qn[d4*4+3], m4.w, a3);
                }
                float x = (a0 + a1) + (a2 + a3);
                if ( x > bestP[r]) { bestP[r] =  x; bpi[r] = n; }
                if (-x > bestN[r]) { bestN[r] = -x; bni[r] = n; }
            }
        }
    }
#pragma unroll
    for (int r = 0; r < 4; ++r) {
        // concat([x, -x]): negative block only wins on strict >
        int idx = (bestN[r] > bestP[r]) ? (64 + bni[r]) : bpi[r];
        g_bkt[((size_t)(b * R_ + r)) * L_ + l] = (unsigned char)idx;
    }
}

// =====================================================================
// K2: stable counting sort per (b,r). Keys = bucket*L + pos, all unique,
// so argsort == stable sort by bucket with position order preserved.
// =====================================================================
__global__ void __launch_bounds__(256) sort_kernel() {
    __shared__ unsigned char bkt_s[L_];
    __shared__ int hist[128];
    __shared__ int basec[128];
    __shared__ int warp_hist[8][128];

    const int tid = threadIdx.x;
    const int br  = blockIdx.x;
    const size_t off = (size_t)br * L_;

    // load bucket ids
    {
        const int4* src = (const int4*)(g_bkt + off);
        int4* dst = (int4*)bkt_s;
        for (int i = tid; i < L_ / 16; i += 256) dst[i] = src[i];
    }
    if (tid < 128) hist[tid] = 0;
    __syncthreads();
    for (int i = tid; i < L_; i += 256) atomicAdd(&hist[bkt_s[i]], 1);
    __syncthreads();
    if (tid == 0) {
        int a = 0;
        for (int c = 0; c < 128; ++c) { basec[c] = a; a += hist[c]; }
    }
    __syncthreads();

    const int lane = tid & 31, w = tid >> 5;
    for (int it = 0; it < L_ / 256; ++it) {
        const int idx = it * 256 + tid;
        const int vv  = bkt_s[idx];
        const unsigned mask = __match_any_sync(0xffffffffu, vv);
        const unsigned lt   = (lane == 0) ? 0u : (0xffffffffu >> (32 - lane));
        const int rank = __popc(mask & lt);
        for (int k = lane; k < 128; k += 32) warp_hist[w][k] = 0;
        __syncwarp();
        if ((mask & lt) == 0) warp_hist[w][vv] = __popc(mask);  // lowest lane of group
        __syncthreads();
        int pre = 0;
        for (int ww = 0; ww < w; ++ww) pre += warp_hist[ww][vv];
        const int dest = basec[vv] + pre + rank;
        g_spos[off + dest] = idx;
        g_sbkt[off + dest] = (unsigned char)vv;
        __syncthreads();
        if (tid < 128) {
            int t2 = 0;
#pragma unroll
            for (int ww = 0; ww < 8; ++ww) t2 += warp_hist[ww][tid];
            basec[tid] += t2;
        }
        __syncthreads();
    }
}

// =====================================================================
// K3: lookback attention per (b, r, chunk). 256 threads.
//   shared: kT [64][KS] keys/queries d-major (raw, reused as p_s),
//           v_s [128][64] values j-major, invn/pos/sh per key slot.
//   thread (i = tid>>2, jq = tid&3): 32 of 128 keys for query row i,
//   softmax across the 4 threads via shuffles, then p@v with the same
//   4 threads split over d.
// =====================================================================
__global__ void __launch_bounds__(256) attend_kernel(const float* __restrict__ q,
                                                     const float* __restrict__ v) {
    extern __shared__ float sm[];
    float* kT     = sm;                       // 64*KS floats (also p_s later)
    float* v_s    = sm + 64 * KS;             // 128*64
    float* invn_s = v_s + 128 * 64;           // 128
    int*   pos_s  = (int*)(invn_s + 128);     // 128
    int*   sh_s   = pos_s + 128;              // 128

    const int tid   = threadIdx.x;
    const int bx    = blockIdx.x;
    const int chunk = bx & (NB_ - 1);
    const int br    = bx >> 7;
    const int b     = br >> 2;
    const int prev  = (chunk + NB_ - 1) & (NB_ - 1);
    const size_t brL = (size_t)br * L_;

    // -------- gather 128 rows (prev chunk = keys 0..63, current = 64..127) -----
    {
        const int lane = tid & 31, w = tid >> 5;
        for (int jr = w; jr < 128; jr += 8) {
            const int slot = (jr < 64) ? prev * BL_ + jr : chunk * BL_ + (jr - 64);
            int pos = 0, bk = 0;
            if (lane == 0) { pos = g_spos[brL + slot]; bk = g_sbkt[brL + slot]; }
            pos = __shfl_sync(0xffffffffu, pos, 0);
            bk  = __shfl_sync(0xffffffffu, bk, 0);
            float ssq = 0.f;
            if (lane < 16) {
                float4 t = *((const float4*)(q + ((size_t)b * L_ + pos) * D_) + lane);
                kT[(lane*4+0)*KS + jr] = t.x;
                kT[(lane*4+1)*KS + jr] = t.y;
                kT[(lane*4+2)*KS + jr] = t.z;
                kT[(lane*4+3)*KS + jr] = t.w;
                ssq = t.x*t.x + t.y*t.y + t.z*t.z + t.w*t.w;
            } else {
                float4 t = *((const float4*)(v + ((size_t)b * L_ + pos) * D_) + (lane - 16));
                *(float4*)(v_s + jr * 64 + (lane - 16) * 4) = t;
            }
#pragma unroll
            for (int o = 16; o > 0; o >>= 1) ssq += __shfl_xor_sync(0xffffffffu, ssq, o);
            if (lane == 0) {
                invn_s[jr] = 1.f / fmaxf(sqrtf(ssq), 1e-12f);
                pos_s[jr]  = pos;
                sh_s[jr]   = bk;
            }
        }
    }
    __syncthreads();

    const int i  = tid >> 2;
    const int jq = tid & 3;
    const int my_sh  = sh_s[64 + i];
    const int my_pos = pos_s[64 + i];
    const float* qcol = kT + 64 + i;      // query d at qcol[d*KS] (raw rq)

    // -------- qk + masks ------------------------------------------------------
    float p[8][4];
#pragma unroll
    for (int g = 0; g < 8; ++g) {
        const int j0 = jq * 4 + g * 16;
        float a0 = 0.f, a1 = 0.f, a2 = 0.f, a3 = 0.f;
        const float4* kp = (const float4*)(kT + j0);
#pragma unroll 16
        for (int d = 0; d < 64; ++d) {
            const float  qd = qcol[d * KS];
            const float4 kv = kp[d * (KS / 4)];
            a0 = fmaf(qd, kv.x, a0);
            a1 = fmaf(qd, kv.y, a1);
            a2 = fmaf(qd, kv.z, a2);
            a3 = fmaf(qd, kv.w, a3);
        }
        float t0 = a0 * invn_s[j0+0] * 0.125f;
        float t1 = a1 * invn_s[j0+1] * 0.125f;
        float t2 = a2 * invn_s[j0+2] * 0.125f;
        float t3 = a3 * invn_s[j0+3] * 0.125f;
        if (my_sh  != sh_s [j0+0]) t0 = -1e9f;
        if (my_sh  != sh_s [j0+1]) t1 = -1e9f;
        if (my_sh  != sh_s [j0+2]) t2 = -1e9f;
        if (my_sh  != sh_s [j0+3]) t3 = -1e9f;
        if (my_pos == pos_s[j0+0]) t0 = -1e5f;
        if (my_pos == pos_s[j0+1]) t1 = -1e5f;
        if (my_pos == pos_s[j0+2]) t2 = -1e5f;
        if (my_pos == pos_s[j0+3]) t3 = -1e5f;
        p[g][0] = t0; p[g][1] = t1; p[g][2] = t2; p[g][3] = t3;
    }

    // -------- softmax over 128 keys (4-thread group per row) -----------------
    float m = -1e30f;
#pragma unroll
    for (int g = 0; g < 8; ++g) {
        m = fmaxf(m, fmaxf(fmaxf(p[g][0], p[g][1]), fmaxf(p[g][2], p[g][3])));
    }
    m = fmaxf(m, __shfl_xor_sync(0xffffffffu, m, 1));
    m = fmaxf(m, __shfl_xor_sync(0xffffffffu, m, 2));
    float s = 0.f;
#pragma unroll
    for (int g = 0; g < 8; ++g)
        s += expf(p[g][0]-m) + expf(p[g][1]-m) + expf(p[g][2]-m) + expf(p[g][3]-m);
    s += __shfl_xor_sync(0xffffffffu, s, 1);
    s += __shfl_xor_sync(0xffffffffu, s, 2);
    const float lse = m + logf(s);
#pragma unroll
    for (int g = 0; g < 8; ++g) {
        p[g][0] = expf(p[g][0] - lse);
        p[g][1] = expf(p[g][1] - lse);
        p[g][2] = expf(p[g][2] - lse);
        p[g][3] = expf(p[g][3] - lse);
    }

    // -------- stage p into shared (reuse kT region) ---------------------------
    __syncthreads();   // all kT reads done
    float* p_s = kT;
#pragma unroll
    for (int g = 0; g < 8; ++g)
        *(float4*)(p_s + i * KS + jq * 4 + g * 16) = make_float4(p[g][0], p[g][1], p[g][2], p[g][3]);
    __syncthreads();

    // -------- att = p @ v ; thread (i, dq) owns d = dq*4 + g*16 + e -----------
    const int dq = jq;
    float4 acc0 = make_float4(0,0,0,0), acc1 = acc0, acc2 = acc0, acc3 = acc0;
    const float* prow = p_s + i * KS;
#pragma unroll 4
    for (int j = 0; j < 128; ++j) {
        const float pv = prow[j];
        const float* vr = v_s + j * 64 + dq * 4;
        float4 v0 = *(const float4*)(vr);
        float4 v1 = *(const float4*)(vr + 16);
        float4 v2 = *(const float4*)(vr + 32);
        float4 v3 = *(const float4*)(vr + 48);
        acc0.x = fmaf(pv, v0.x, acc0.x); acc0.y = fmaf(pv, v0.y, acc0.y);
        acc0.z = fmaf(pv, v0.z, acc0.z); acc0.w = fmaf(pv, v0.w, acc0.w);
        acc1.x = fmaf(pv, v1.x, acc1.x); acc1.y = fmaf(pv, v1.y, acc1.y);
        acc1.z = fmaf(pv, v1.z, acc1.z); acc1.w = fmaf(pv, v1.w, acc1.w);
        acc2.x = fmaf(pv, v2.x, acc2.x); acc2.y = fmaf(pv, v2.y, acc2.y);
        acc2.z = fmaf(pv, v2.z, acc2.z); acc2.w = fmaf(pv, v2.w, acc2.w);
        acc3.x = fmaf(pv, v3.x, acc3.x); acc3.y = fmaf(pv, v3.y, acc3.y);
        acc3.z = fmaf(pv, v3.z, acc3.z); acc3.w = fmaf(pv, v3.w, acc3.w);
    }

    float* orow = g_att + (brL + (size_t)my_pos) * D_;   // scatter to original position
    *(float4*)(orow + dq * 4)      = acc0;
    *(float4*)(orow + dq * 4 + 16) = acc1;
    *(float4*)(orow + dq * 4 + 32) = acc2;
    *(float4*)(orow + dq * 4 + 48) = acc3;
    if (jq == 0) g_lse[brL + (size_t)my_pos] = lse;
}

// =====================================================================
// K4: per-(b,r) softmax normalizer over L: m = max lse, z = sum exp(lse-m)
// =====================================================================
__global__ void __launch_bounds__(256) lse_reduce_kernel() {
    __shared__ float red[256];
    const int br = blockIdx.x, tid = threadIdx.x;
    const size_t off = (size_t)br * L_;
    float m = -1e30f;
    for (int i = tid; i < L_; i += 256) m = fmaxf(m, g_lse[off + i]);
    red[tid] = m; __syncthreads();
    for (int s2 = 128; s2 > 0; s2 >>= 1) {
        if (tid < s2) red[tid] = fmaxf(red[tid], red[tid + s2]);
        __syncthreads();
    }
    const float mm = red[0];
    __syncthreads();
    float s = 0.f;
    for (int i = tid; i < L_; i += 256) s += expf(g_lse[off + i] - mm);
    red[tid] = s; __syncthreads();
    for (int s2 = 128; s2 > 0; s2 >>= 1) {
        if (tid < s2) red[tid] += red[tid + s2];
        __syncthreads();
    }
    if (tid == 0) { g_m[br] = mm; g_z[br] = red[0]; }
}

// =====================================================================
// K5: out[b,l,d] = sum_r att[b,r,l,d] * exp(lse[b,r,l]-m[b,r]) / z[b,r]
// =====================================================================
__global__ void __launch_bounds__(256) combine_kernel(float* __restrict__ out) {
    const int tid = threadIdx.x;
    const int gl  = blockIdx.x * 4 + (tid >> 6);   // global row in [0, B*L)
    const int d   = tid & 63;
    const int b   = gl >> 13;                       // L = 8192
    const int l   = gl & (L_ - 1);
    float acc = 0.f;
#pragma unroll
    for (int r = 0; r < 4; ++r) {
        const int br = b * 4 + r;
        const size_t row = (size_t)br * L_ + l;
        const float w = expf(g_lse[row] - g_m[br]) / g_z[br];
        acc = fmaf(g_att[row * D_ + d], w, acc);
    }
    out[(size_t)gl * D_ + d] = acc;
}

// =====================================================================
extern "C" void kernel_launch(void* const* d_in, const int* in_sizes, int n_in,
                              void* d_out, int out_size) {
    const float* q   = (const float*)d_in[0];
    const float* v   = (const float*)d_in[1];
    const float* rmt = (const float*)d_in[2];
    float* out = (float*)d_out;
    (void)in_sizes; (void)n_in; (void)out_size;

    const int att_smem = (64 * KS + 128 * 64 + 128) * (int)sizeof(float) + 256 * (int)sizeof(int);
    cudaFuncSetAttribute(attend_kernel, cudaFuncAttributeMaxDynamicSharedMemorySize, att_smem);

    hash_kernel<<<dim3(L_ / 128, B_), 128>>>(q, rmt);
    sort_kernel<<<B_ * R_, 256>>>();
    attend_kernel<<<B_ * R_ * NB_, 256, att_smem>>>(q, v);
    lse_reduce_kernel<<<B_ * R_, 256>>>();
    combine_kernel<<<B_ * L_ / 4, 256>>>(out);
}

// round 11
// speedup vs baseline: 1.5673x; 1.5671x over previous
#include <cuda_runtime.h>
#include <cuda_fp16.h>
#include <math.h>

#define B_   16
#define L_   8192
#define D_   64
#define R_   4
#define NB_  128     // n_buckets = chunks per (b,r)
#define BL_  64      // bucket length (chunk size)

#define KSTR 68      // k_s row stride (floats): 128 rows x 64 d
#define PSTR 132     // p_s row stride (floats): 64 rows x 128 j
#define VSTR 130     // v_sT row stride (floats): 64 d-rows x 128 j

// ---------------- scratch (static device memory; no allocations) ----------------
__device__ __align__(16) __half        g_att[(size_t)B_*R_*L_*D_];   // 67 MB fp16: per-round att, original order
__device__ __align__(16) float         g_lse[B_*R_*L_];
__device__ __align__(16) int           g_spos[B_*R_*L_];
__device__ __align__(16) unsigned char g_sbkt[B_*R_*L_];
__device__ __align__(16) unsigned char g_bkt[B_*R_*L_];
__device__ float g_m[B_*R_];
__device__ float g_z[B_*R_];

// ---------------- packed f32x2 helpers (Blackwell FFMA2 path) ----------------
__device__ __forceinline__ unsigned long long ffma2(unsigned long long a,
                                                    unsigned long long b,
                                                    unsigned long long c) {
    unsigned long long d;
    asm("fma.rn.f32x2 %0, %1, %2, %3;" : "=l"(d) : "l"(a), "l"(b), "l"(c));
    return d;
}
__device__ __forceinline__ unsigned long long pack2(float lo, float hi) {
    unsigned long long r;
    asm("mov.b64 %0, {%1, %2};" : "=l"(r) : "f"(lo), "f"(hi));
    return r;
}
__device__ __forceinline__ float2 unpack2(unsigned long long v) {
    float2 r;
    asm("mov.b64 {%0, %1}, %2;" : "=f"(r.x), "=f"(r.y) : "l"(v));
    return r;
}

// =====================================================================
// K1: LSH hash, f32x2 packed dot products.
// =====================================================================
__global__ void __launch_bounds__(128) hash_kernel(const float* __restrict__ q,
                                                   const float* __restrict__ rmat) {
    __shared__ float rm_s[128 * 64];   // [col][d]
    const int tid = threadIdx.x;
    const int b   = blockIdx.y;
    const int l   = blockIdx.x * 128 + tid;

    // load + normalize query row, then pack d-pairs
    float qn[64];
    float ss = 0.f;
    const float4* qrow = (const float4*)(q + ((size_t)b * L_ + l) * D_);
#pragma unroll
    for (int d4 = 0; d4 < 16; ++d4) {
        float4 t = qrow[d4];
        qn[d4*4+0] = t.x; qn[d4*4+1] = t.y; qn[d4*4+2] = t.z; qn[d4*4+3] = t.w;
        ss += t.x*t.x + t.y*t.y + t.z*t.z + t.w*t.w;
    }
    const float inq = 1.f / fmaxf(sqrtf(ss), 1e-12f);
    unsigned long long qn2[32];
#pragma unroll
    for (int d2 = 0; d2 < 32; ++d2) qn2[d2] = pack2(qn[2*d2] * inq, qn[2*d2+1] * inq);

    float bestP[4], bestN[4];
    int   bpi[4],   bni[4];
#pragma unroll
    for (int r = 0; r < 4; ++r) { bestP[r] = -1e30f; bestN[r] = -1e30f; bpi[r] = 0; bni[r] = 0; }

    const float* rm_b = rmat + (size_t)b * D_ * R_ * 64;  // [d][c], row stride 256

#pragma unroll
    for (int half = 0; half < 2; ++half) {
        __syncthreads();
        for (int i = tid; i < 128 * 64; i += 128) {
            int d  = i >> 7;
            int cl = i & 127;
            rm_s[cl * 64 + d] = rm_b[d * 256 + half * 128 + cl];
        }
        __syncthreads();
        {   // normalize column `tid` over d
            float s2 = 0.f;
#pragma unroll 8
            for (int d = 0; d < 64; ++d) { float x = rm_s[tid * 64 + d]; s2 += x * x; }
            float inv = 1.f / fmaxf(sqrtf(s2), 1e-12f);
#pragma unroll 8
            for (int d = 0; d < 64; ++d) rm_s[tid * 64 + d] *= inv;
        }
        __syncthreads();
#pragma unroll
        for (int r_loc = 0; r_loc < 2; ++r_loc) {
            const int r = half * 2 + r_loc;
            for (int n = 0; n < 64; ++n) {
                const ulonglong2* col = (const ulonglong2*)(rm_s + (r_loc * 64 + n) * 64);
                unsigned long long a0 = 0ull, a1 = 0ull, a2 = 0ull, a3 = 0ull;
#pragma unroll
                for (int d4 = 0; d4 < 16; d4 += 2) {
                    ulonglong2 m0 = col[d4];
                    ulonglong2 m1 = col[d4 + 1];
                    a0 = ffma2(qn2[2*d4+0], m0.x, a0);
                    a1 = ffma2(qn2[2*d4+1], m0.y, a1);
                    a2 = ffma2(qn2[2*d4+2], m1.x, a2);
                    a3 = ffma2(qn2[2*d4+3], m1.y, a3);
                }
                float2 u0 = unpack2(a0), u1 = unpack2(a1), u2 = unpack2(a2), u3 = unpack2(a3);
                float x = ((u0.x + u0.y) + (u1.x + u1.y)) + ((u2.x + u2.y) + (u3.x + u3.y));
                if ( x > bestP[r]) { bestP[r] =  x; bpi[r] = n; }
                if (-x > bestN[r]) { bestN[r] = -x; bni[r] = n; }
            }
        }
    }
#pragma unroll
    for (int r = 0; r < 4; ++r) {
        int idx = (bestN[r] > bestP[r]) ? (64 + bni[r]) : bpi[r];
        g_bkt[((size_t)(b * R_ + r)) * L_ + l] = (unsigned char)idx;
    }
}

// =====================================================================
// K2: stable counting sort per (b,r).  (unchanged — ~10us total)
// =====================================================================
__global__ void __launch_bounds__(256) sort_kernel() {
    __shared__ unsigned char bkt_s[L_];
    __shared__ int hist[128];
    __shared__ int basec[128];
    __shared__ int warp_hist[8][128];

    const int tid = threadIdx.x;
    const int br  = blockIdx.x;
    const size_t off = (size_t)br * L_;

    {
        const int4* src = (const int4*)(g_bkt + off);
        int4* dst = (int4*)bkt_s;
        for (int i = tid; i < L_ / 16; i += 256) dst[i] = src[i];
    }
    if (tid < 128) hist[tid] = 0;
    __syncthreads();
    for (int i = tid; i < L_; i += 256) atomicAdd(&hist[bkt_s[i]], 1);
    __syncthreads();
    if (tid == 0) {
        int a = 0;
        for (int c = 0; c < 128; ++c) { basec[c] = a; a += hist[c]; }
    }
    __syncthreads();

    const int lane = tid & 31, w = tid >> 5;
    for (int it = 0; it < L_ / 256; ++it) {
        const int idx = it * 256 + tid;
        const int vv  = bkt_s[idx];
        const unsigned mask = __match_any_sync(0xffffffffu, vv);
        const unsigned lt   = (lane == 0) ? 0u : (0xffffffffu >> (32 - lane));
        const int rank = __popc(mask & lt);
        for (int k = lane; k < 128; k += 32) warp_hist[w][k] = 0;
        __syncwarp();
        if ((mask & lt) == 0) warp_hist[w][vv] = __popc(mask);
        __syncthreads();
        int pre = 0;
        for (int ww = 0; ww < w; ++ww) pre += warp_hist[ww][vv];
        const int dest = basec[vv] + pre + rank;
        g_spos[off + dest] = idx;
        g_sbkt[off + dest] = (unsigned char)vv;
        __syncthreads();
        if (tid < 128) {
            int t2 = 0;
#pragma unroll
            for (int ww = 0; ww < 8; ++ww) t2 += warp_hist[ww][tid];
            basec[tid] += t2;
        }
        __syncthreads();
    }
}

// =====================================================================
// K3: lookback attention, f32x2 packed GEMMs.
//   k_s [128][KSTR]  keys (raw q rows), row-major d-contig (reused as p_s)
//   v_sT [64][VSTR]  values transposed: v_sT[d][j]
//   qk: thread (ti=tid>>4, tj=tid&15) -> i-tile ti*4+ii, j-tile tj+16*jj
//       acc over packed d-pairs (no mov packing).
//   pv: same i-tile, d set td+16g; acc over packed j-parity pairs.
// =====================================================================
__global__ void __launch_bounds__(256, 2) attend_kernel(const float* __restrict__ q,
                                                        const float* __restrict__ v) {
    extern __shared__ float sm[];
    float* k_s    = sm;                       // 128*KSTR = 8704 floats (p_s overlay: 64*PSTR = 8448)
    float* v_sT   = sm + 128 * KSTR;          // 64*VSTR = 8320
    float* invn_s = v_sT + 64 * VSTR;         // 128
    int*   pos_s  = (int*)(invn_s + 128);     // 128
    int*   sh_s   = pos_s + 128;              // 128

    const int tid   = threadIdx.x;
    const int bx    = blockIdx.x;
    const int chunk = bx & (NB_ - 1);
    const int br    = bx >> 7;
    const int b     = br >> 2;
    const int prev  = (chunk + NB_ - 1) & (NB_ - 1);
    const size_t brL = (size_t)br * L_;

    // -------- gather 128 rows: prev chunk = 0..63, current = 64..127 ----------
    {
        const int lane = tid & 31, w = tid >> 5;
        for (int jr = w; jr < 128; jr += 8) {
            const int slot = (jr < 64) ? prev * BL_ + jr : chunk * BL_ + (jr - 64);
            int pos = 0, bk = 0;
            if (lane == 0) { pos = g_spos[brL + slot]; bk = g_sbkt[brL + slot]; }
            pos = __shfl_sync(0xffffffffu, pos, 0);
            bk  = __shfl_sync(0xffffffffu, bk, 0);
            float ssq = 0.f;
            if (lane < 16) {
                float4 t = *((const float4*)(q + ((size_t)b * L_ + pos) * D_) + lane);
                *(float4*)(k_s + jr * KSTR + lane * 4) = t;
                ssq = t.x*t.x + t.y*t.y + t.z*t.z + t.w*t.w;
            } else {
                float4 t = *((const float4*)(v + ((size_t)b * L_ + pos) * D_) + (lane - 16));
                const int d0 = (lane - 16) * 4;
                v_sT[(d0 + 0) * VSTR + jr] = t.x;
                v_sT[(d0 + 1) * VSTR + jr] = t.y;
                v_sT[(d0 + 2) * VSTR + jr] = t.z;
                v_sT[(d0 + 3) * VSTR + jr] = t.w;
            }
#pragma unroll
            for (int o = 16; o > 0; o >>= 1) ssq += __shfl_xor_sync(0xffffffffu, ssq, o);
            if (lane == 0) {
                invn_s[jr] = 1.f / fmaxf(sqrtf(ssq), 1e-12f);
                pos_s[jr]  = pos;
                sh_s[jr]   = bk;
            }
        }
    }
    __syncthreads();

    const int tj = tid & 15;
    const int ti = tid >> 4;
    const int i0 = ti * 4;

    int   my_pos[4], my_sh[4];
#pragma unroll
    for (int ii = 0; ii < 4; ++ii) {
        my_pos[ii] = pos_s[64 + i0 + ii];
        my_sh[ii]  = sh_s [64 + i0 + ii];
    }

    // -------- qk: packed over d-pairs --------------------------------------
    const ulonglong2* qr[4];
    const ulonglong2* kr[8];
#pragma unroll
    for (int ii = 0; ii < 4; ++ii) qr[ii] = (const ulonglong2*)(k_s + (64 + i0 + ii) * KSTR);
#pragma unroll
    for (int jj = 0; jj < 8; ++jj) kr[jj] = (const ulonglong2*)(k_s + (tj + 16 * jj) * KSTR);

    unsigned long long acc[4][8];
#pragma unroll
    for (int ii = 0; ii < 4; ++ii)
#pragma unroll
        for (int jj = 0; jj < 8; ++jj) acc[ii][jj] = 0ull;

#pragma unroll 4
    for (int ds = 0; ds < 16; ++ds) {
        ulonglong2 qv[4];
#pragma unroll
        for (int ii = 0; ii < 4; ++ii) qv[ii] = qr[ii][ds];
#pragma unroll
        for (int jj = 0; jj < 8; ++jj) {
            ulonglong2 kv = kr[jj][ds];
#pragma unroll
            for (int ii = 0; ii < 4; ++ii) {
                acc[ii][jj] = ffma2(qv[ii].x, kv.x, acc[ii][jj]);
                acc[ii][jj] = ffma2(qv[ii].y, kv.y, acc[ii][jj]);
            }
        }
    }

    // -------- scores + masks ------------------------------------------------
    float p[4][8];
#pragma unroll
    for (int jj = 0; jj < 8; ++jj) {
        const int j = tj + 16 * jj;
        const float sc = invn_s[j] * 0.125f;
        const int   shj = sh_s[j];
        const int   psj = pos_s[j];
#pragma unroll
        for (int ii = 0; ii < 4; ++ii) {
            float2 u = unpack2(acc[ii][jj]);
            float t = (u.x + u.y) * sc;
            if (my_sh[ii]  != shj) t = -1e9f;
            if (my_pos[ii] == psj) t = -1e5f;
            p[ii][jj] = t;
        }
    }

    // -------- softmax over 128 keys (16-thread group per i-row) ------------
    float m[4], s[4], lse[4];
#pragma unroll
    for (int ii = 0; ii < 4; ++ii) {
        float mm = p[ii][0];
#pragma unroll
        for (int jj = 1; jj < 8; ++jj) mm = fmaxf(mm, p[ii][jj]);
        m[ii] = mm;
    }
#pragma unroll
    for (int o = 1; o < 16; o <<= 1)
#pragma unroll
        for (int ii = 0; ii < 4; ++ii)
            m[ii] = fmaxf(m[ii], __shfl_xor_sync(0xffffffffu, m[ii], o));
#pragma unroll
    for (int ii = 0; ii < 4; ++ii) {
        float ss2 = 0.f;
#pragma unroll
        for (int jj = 0; jj < 8; ++jj) { p[ii][jj] = expf(p[ii][jj] - m[ii]); ss2 += p[ii][jj]; }
        s[ii] = ss2;
    }
#pragma unroll
    for (int o = 1; o < 16; o <<= 1)
#pragma unroll
        for (int ii = 0; ii < 4; ++ii)
            s[ii] += __shfl_xor_sync(0xffffffffu, s[ii], o);
#pragma unroll
    for (int ii = 0; ii < 4; ++ii) {
        lse[ii] = m[ii] + logf(s[ii]);
        const float inv = 1.f / s[ii];
#pragma unroll
        for (int jj = 0; jj < 8; ++jj) p[ii][jj] *= inv;
    }
    if (tj == 0) {
#pragma unroll
        for (int ii = 0; ii < 4; ++ii) g_lse[brL + (size_t)my_pos[ii]] = lse[ii];
    }

    // -------- stage p into shared (overlay k_s) ----------------------------
    __syncthreads();   // all k_s reads done
    float* p_s = k_s;  // stride PSTR
#pragma unroll
    for (int ii = 0; ii < 4; ++ii)
#pragma unroll
        for (int jj = 0; jj < 8; ++jj)
            p_s[(i0 + ii) * PSTR + tj + 16 * jj] = p[ii][jj];
    __syncthreads();

    // -------- att = p @ v : packed over j-parity pairs ---------------------
    const int td = tj;   // d set: td + 16g
    const ulonglong2* pr[4];
#pragma unroll
    for (int ii = 0; ii < 4; ++ii) pr[ii] = (const ulonglong2*)(p_s + (i0 + ii) * PSTR);
    const unsigned long long* vr[4];
#pragma unroll
    for (int g = 0; g < 4; ++g) vr[g] = (const unsigned long long*)(v_sT + (td + 16 * g) * VSTR);

    unsigned long long accv[4][4];
#pragma unroll
    for (int ii = 0; ii < 4; ++ii)
#pragma unroll
        for (int g = 0; g < 4; ++g) accv[ii][g] = 0ull;

#pragma unroll 4
    for (int jp2 = 0; jp2 < 32; ++jp2) {
        ulonglong2 pp[4];
#pragma unroll
        for (int ii = 0; ii < 4; ++ii) pp[ii] = pr[ii][jp2];
#pragma unroll
        for (int g = 0; g < 4; ++g) {
            const unsigned long long v0 = vr[g][2 * jp2 + 0];
            const unsigned long long v1 = vr[g][2 * jp2 + 1];
#pragma unroll
            for (int ii = 0; ii < 4; ++ii) {
                accv[ii][g] = ffma2(pp[ii].x, v0, accv[ii][g]);
                accv[ii][g] = ffma2(pp[ii].y, v1, accv[ii][g]);
            }
        }
    }

#pragma unroll
    for (int ii = 0; ii < 4; ++ii) {
        __half* orow = g_att + (brL + (size_t)my_pos[ii]) * D_;
#pragma unroll
        for (int g = 0; g < 4; ++g) {
            float2 u = unpack2(accv[ii][g]);
            orow[td + 16 * g] = __float2half(u.x + u.y);
        }
    }
}

// =====================================================================
// K4: per-(b,r) softmax normalizer over L.
// =====================================================================
__global__ void __launch_bounds__(256) lse_reduce_kernel() {
    __shared__ float red[256];
    const int br = blockIdx.x, tid = threadIdx.x;
    const size_t off = (size_t)br * L_;
    float m = -1e30f;
    for (int i = tid; i < L_; i += 256) m = fmaxf(m, g_lse[off + i]);
    red[tid] = m; __syncthreads();
    for (int s2 = 128; s2 > 0; s2 >>= 1) {
        if (tid < s2) red[tid] = fmaxf(red[tid], red[tid + s2]);
        __syncthreads();
    }
    const float mm = red[0];
    __syncthreads();
    float s = 0.f;
    for (int i = tid; i < L_; i += 256) s += expf(g_lse[off + i] - mm);
    red[tid] = s; __syncthreads();
    for (int s2 = 128; s2 > 0; s2 >>= 1) {
        if (tid < s2) red[tid] += red[tid + s2];
        __syncthreads();
    }
    if (tid == 0) { g_m[br] = mm; g_z[br] = red[0]; }
}

// =====================================================================
// K5: out[b,l,d] = sum_r att[b,r,l,d] * exp(lse[b,r,l]-m[b,r]) / z[b,r]
// =====================================================================
__global__ void __launch_bounds__(256) combine_kernel(float* __restrict__ out) {
    const int tid = threadIdx.x;
    const int gl  = blockIdx.x * 4 + (tid >> 6);
    const int d   = tid & 63;
    const int b   = gl >> 13;
    const int l   = gl & (L_ - 1);
    float acc = 0.f;
#pragma unroll
    for (int r = 0; r < 4; ++r) {
        const int br = b * 4 + r;
        const size_t row = (size_t)br * L_ + l;
        const float w = expf(g_lse[row] - g_m[br]) / g_z[br];
        acc = fmaf(__half2float(g_att[row * D_ + d]), w, acc);
    }
    out[(size_t)gl * D_ + d] = acc;
}

// =====================================================================
extern "C" void kernel_launch(void* const* d_in, const int* in_sizes, int n_in,
                              void* d_out, int out_size) {
    const float* q   = (const float*)d_in[0];
    const float* v   = (const float*)d_in[1];
    const float* rmt = (const float*)d_in[2];
    float* out = (float*)d_out;
    (void)in_sizes; (void)n_in; (void)out_size;

    const int att_smem = (128 * KSTR + 64 * VSTR + 128) * (int)sizeof(float)
                       + 256 * (int)sizeof(int);
    cudaFuncSetAttribute(attend_kernel, cudaFuncAttributeMaxDynamicSharedMemorySize, att_smem);

    hash_kernel<<<dim3(L_ / 128, B_), 128>>>(q, rmt);
    sort_kernel<<<B_ * R_, 256>>>();
    attend_kernel<<<B_ * R_ * NB_, 256, att_smem>>>(q, v);
    lse_reduce_kernel<<<B_ * R_, 256>>>();
    combine_kernel<<<B_ * L_ / 4, 256>>>(out);
}

// round 12
// speedup vs baseline: 1.8514x; 1.1813x over previous
#include <cuda_runtime.h>
#include <cuda_fp16.h>
#include <math.h>

#define B_   16
#define L_   8192
#define D_   64
#define R_   4
#define NB_  128     // n_buckets = chunks per (b,r)
#define BL_  64      // bucket length (chunk size)

#define KSTR 68      // k_s / p_sT / v_s row stride (floats)

// ---------------- scratch (static device memory; no allocations) ----------------
__device__ __align__(16) __half        g_att[(size_t)B_*R_*L_*D_];   // 67 MB fp16
__device__ __align__(16) float         g_lse[B_*R_*L_];
__device__ __align__(16) int           g_spos[B_*R_*L_];
__device__ __align__(16) unsigned char g_sbkt[B_*R_*L_];
__device__ __align__(16) unsigned char g_bkt[B_*R_*L_];
__device__ float g_m[B_*R_];
__device__ float g_z[B_*R_];

// ---------------- packed f32x2 helpers (Blackwell FFMA2 path) ----------------
__device__ __forceinline__ unsigned long long ffma2(unsigned long long a,
                                                    unsigned long long b,
                                                    unsigned long long c) {
    unsigned long long d;
    asm("fma.rn.f32x2 %0, %1, %2, %3;" : "=l"(d) : "l"(a), "l"(b), "l"(c));
    return d;
}
__device__ __forceinline__ unsigned long long fmul2(unsigned long long a,
                                                    unsigned long long b) {
    unsigned long long d;
    asm("mul.rn.f32x2 %0, %1, %2;" : "=l"(d) : "l"(a), "l"(b));
    return d;
}
__device__ __forceinline__ unsigned long long pack2(float lo, float hi) {
    unsigned long long r;
    asm("mov.b64 %0, {%1, %2};" : "=l"(r) : "f"(lo), "f"(hi));
    return r;
}
__device__ __forceinline__ float2 unpack2(unsigned long long v) {
    float2 r;
    asm("mov.b64 {%0, %1}, %2;" : "=f"(r.x), "=f"(r.y) : "l"(v));
    return r;
}

// =====================================================================
// K1: LSH hash. Conflict-free staging: thread tid owns column tid
// (accumulates sumsq during load); 1/norm folded into dot epilogue.
// =====================================================================
__global__ void __launch_bounds__(128) hash_kernel(const float* __restrict__ q,
                                                   const float* __restrict__ rmat) {
    __shared__ float rm_s[128 * KSTR];   // [col][d], stride 68
    __shared__ float invc_s[128];
    const int tid = threadIdx.x;
    const int b   = blockIdx.y;
    const int l   = blockIdx.x * 128 + tid;

    // load + normalize query row, then pack d-pairs
    float qn[64];
    float ss = 0.f;
    const float4* qrow = (const float4*)(q + ((size_t)b * L_ + l) * D_);
#pragma unroll
    for (int d4 = 0; d4 < 16; ++d4) {
        float4 t = qrow[d4];
        qn[d4*4+0] = t.x; qn[d4*4+1] = t.y; qn[d4*4+2] = t.z; qn[d4*4+3] = t.w;
        ss += t.x*t.x + t.y*t.y + t.z*t.z + t.w*t.w;
    }
    const float inq = 1.f / fmaxf(sqrtf(ss), 1e-12f);
    unsigned long long qn2[32];
#pragma unroll
    for (int d2 = 0; d2 < 32; ++d2) qn2[d2] = pack2(qn[2*d2] * inq, qn[2*d2+1] * inq);

    float bestP[4], bestN[4];
    int   bpi[4],   bni[4];
#pragma unroll
    for (int r = 0; r < 4; ++r) { bestP[r] = -1e30f; bestN[r] = -1e30f; bpi[r] = 0; bni[r] = 0; }

    const float* rm_b = rmat + (size_t)b * D_ * R_ * 64;  // [d][c], row stride 256

#pragma unroll
    for (int half = 0; half < 2; ++half) {
        __syncthreads();
        // thread tid loads+stages column tid of this half; sumsq on the fly
        {
            float s2 = 0.f;
#pragma unroll 16
            for (int k = 0; k < 64; ++k) {
                float x = rm_b[k * 256 + half * 128 + tid];  // coalesced
                rm_s[tid * KSTR + k] = x;
                s2 += x * x;
            }
            invc_s[tid] = 1.f / fmaxf(sqrtf(s2), 1e-12f);
        }
        __syncthreads();
#pragma unroll
        for (int r_loc = 0; r_loc < 2; ++r_loc) {
            const int r = half * 2 + r_loc;
#pragma unroll 2
            for (int n = 0; n < 64; ++n) {
                const int cl = r_loc * 64 + n;
                const ulonglong2* col = (const ulonglong2*)(rm_s + cl * KSTR);
                unsigned long long a0 = 0ull, a1 = 0ull, a2 = 0ull, a3 = 0ull;
#pragma unroll
                for (int d4 = 0; d4 < 16; d4 += 2) {
                    ulonglong2 m0 = col[d4];
                    ulonglong2 m1 = col[d4 + 1];
                    a0 = ffma2(qn2[2*d4+0], m0.x, a0);
                    a1 = ffma2(qn2[2*d4+1], m0.y, a1);
                    a2 = ffma2(qn2[2*d4+2], m1.x, a2);
                    a3 = ffma2(qn2[2*d4+3], m1.y, a3);
                }
                float2 u0 = unpack2(a0), u1 = unpack2(a1), u2 = unpack2(a2), u3 = unpack2(a3);
                float x = (((u0.x + u0.y) + (u1.x + u1.y)) + ((u2.x + u2.y) + (u3.x + u3.y)))
                          * invc_s[cl];
                if ( x > bestP[r]) { bestP[r] =  x; bpi[r] = n; }
                if (-x > bestN[r]) { bestN[r] = -x; bni[r] = n; }
            }
        }
    }
#pragma unroll
    for (int r = 0; r < 4; ++r) {
        int idx = (bestN[r] > bestP[r]) ? (64 + bni[r]) : bpi[r];
        g_bkt[((size_t)(b * R_ + r)) * L_ + l] = (unsigned char)idx;
    }
}

// =====================================================================
// K2: stable counting sort per (b,r).  (unchanged)
// =====================================================================
__global__ void __launch_bounds__(256) sort_kernel() {
    __shared__ unsigned char bkt_s[L_];
    __shared__ int hist[128];
    __shared__ int basec[128];
    __shared__ int warp_hist[8][128];

    const int tid = threadIdx.x;
    const int br  = blockIdx.x;
    const size_t off = (size_t)br * L_;

    {
        const int4* src = (const int4*)(g_bkt + off);
        int4* dst = (int4*)bkt_s;
        for (int i = tid; i < L_ / 16; i += 256) dst[i] = src[i];
    }
    if (tid < 128) hist[tid] = 0;
    __syncthreads();
    for (int i = tid; i < L_; i += 256) atomicAdd(&hist[bkt_s[i]], 1);
    __syncthreads();
    if (tid == 0) {
        int a = 0;
        for (int c = 0; c < 128; ++c) { basec[c] = a; a += hist[c]; }
    }
    __syncthreads();

    const int lane = tid & 31, w = tid >> 5;
    for (int it = 0; it < L_ / 256; ++it) {
        const int idx = it * 256 + tid;
        const int vv  = bkt_s[idx];
        const unsigned mask = __match_any_sync(0xffffffffu, vv);
        const unsigned lt   = (lane == 0) ? 0u : (0xffffffffu >> (32 - lane));
        const int rank = __popc(mask & lt);
        for (int k = lane; k < 128; k += 32) warp_hist[w][k] = 0;
        __syncwarp();
        if ((mask & lt) == 0) warp_hist[w][vv] = __popc(mask);
        __syncthreads();
        int pre = 0;
        for (int ww = 0; ww < w; ++ww) pre += warp_hist[ww][vv];
        const int dest = basec[vv] + pre + rank;
        g_spos[off + dest] = idx;
        g_sbkt[off + dest] = (unsigned char)vv;
        __syncthreads();
        if (tid < 128) {
            int t2 = 0;
#pragma unroll
            for (int ww = 0; ww < 8; ++ww) t2 += warp_hist[ww][tid];
            basec[tid] += t2;
        }
        __syncthreads();
    }
}

// =====================================================================
// K3: lookback attention.
//   k_s  [128][KSTR] keys (raw q rows), d-contig — reused as p_sT after qk
//   v_s  [128][KSTR] values ROW-major (conflict-free gather)
//   qk:  thread (ti=tid>>4, tj=tid&15), i-tile ti*4+ii, j = tj+16*jj,
//        packed d-pairs (unchanged from R10).
//   p:   stored transposed p_sT[j][i] (unnormalized exp) so pv loads
//        LDS.128 => two pre-packed i-pairs for FFMA2.
//   pv:  thread owns i-tile x 4 consecutive d (tj*4); 1/s folded into
//        the f32x2 epilogue.
// =====================================================================
__global__ void __launch_bounds__(256, 2) attend_kernel(const float* __restrict__ q,
                                                        const float* __restrict__ v) {
    extern __shared__ float sm[];
    float* k_s    = sm;                       // 128*KSTR (p_sT overlay, same size)
    float* v_s    = sm + 128 * KSTR;          // 128*KSTR row-major [j][d]
    float* invn_s = v_s + 128 * KSTR;         // 128
    int*   pos_s  = (int*)(invn_s + 128);     // 128
    int*   sh_s   = pos_s + 128;              // 128

    const int tid   = threadIdx.x;
    const int bx    = blockIdx.x;
    const int chunk = bx & (NB_ - 1);
    const int br    = bx >> 7;
    const int b     = br >> 2;
    const int prev  = (chunk + NB_ - 1) & (NB_ - 1);
    const size_t brL = (size_t)br * L_;

    // -------- gather 128 rows: prev chunk = 0..63, current = 64..127 ----------
    {
        const int lane = tid & 31, w = tid >> 5;
        for (int jr = w; jr < 128; jr += 8) {
            const int slot = (jr < 64) ? prev * BL_ + jr : chunk * BL_ + (jr - 64);
            int pos = 0, bk = 0;
            if (lane == 0) { pos = g_spos[brL + slot]; bk = g_sbkt[brL + slot]; }
            pos = __shfl_sync(0xffffffffu, pos, 0);
            bk  = __shfl_sync(0xffffffffu, bk, 0);
            float ssq = 0.f;
            if (lane < 16) {
                float4 t = *((const float4*)(q + ((size_t)b * L_ + pos) * D_) + lane);
                *(float4*)(k_s + jr * KSTR + lane * 4) = t;
                ssq = t.x*t.x + t.y*t.y + t.z*t.z + t.w*t.w;
            } else {
                float4 t = *((const float4*)(v + ((size_t)b * L_ + pos) * D_) + (lane - 16));
                *(float4*)(v_s + jr * KSTR + (lane - 16) * 4) = t;   // row-major, no conflicts
            }
#pragma unroll
            for (int o = 16; o > 0; o >>= 1) ssq += __shfl_xor_sync(0xffffffffu, ssq, o);
            if (lane == 0) {
                invn_s[jr] = 1.f / fmaxf(sqrtf(ssq), 1e-12f);
                pos_s[jr]  = pos;
                sh_s[jr]   = bk;
            }
        }
    }
    __syncthreads();

    const int tj = tid & 15;
    const int ti = tid >> 4;
    const int i0 = ti * 4;

    int   my_pos[4], my_sh[4];
#pragma unroll
    for (int ii = 0; ii < 4; ++ii) {
        my_pos[ii] = pos_s[64 + i0 + ii];
        my_sh[ii]  = sh_s [64 + i0 + ii];
    }

    // -------- qk: packed over d-pairs --------------------------------------
    const ulonglong2* qr[4];
    const ulonglong2* kr[8];
#pragma unroll
    for (int ii = 0; ii < 4; ++ii) qr[ii] = (const ulonglong2*)(k_s + (64 + i0 + ii) * KSTR);
#pragma unroll
    for (int jj = 0; jj < 8; ++jj) kr[jj] = (const ulonglong2*)(k_s + (tj + 16 * jj) * KSTR);

    unsigned long long acc[4][8];
#pragma unroll
    for (int ii = 0; ii < 4; ++ii)
#pragma unroll
        for (int jj = 0; jj < 8; ++jj) acc[ii][jj] = 0ull;

#pragma unroll 4
    for (int ds = 0; ds < 16; ++ds) {
        ulonglong2 qv[4];
#pragma unroll
        for (int ii = 0; ii < 4; ++ii) qv[ii] = qr[ii][ds];
#pragma unroll
        for (int jj = 0; jj < 8; ++jj) {
            ulonglong2 kv = kr[jj][ds];
#pragma unroll
            for (int ii = 0; ii < 4; ++ii) {
                acc[ii][jj] = ffma2(qv[ii].x, kv.x, acc[ii][jj]);
                acc[ii][jj] = ffma2(qv[ii].y, kv.y, acc[ii][jj]);
            }
        }
    }

    // -------- scores + masks ------------------------------------------------
    float p[4][8];
#pragma unroll
    for (int jj = 0; jj < 8; ++jj) {
        const int j = tj + 16 * jj;
        const float sc = invn_s[j] * 0.125f;
        const int   shj = sh_s[j];
        const int   psj = pos_s[j];
#pragma unroll
        for (int ii = 0; ii < 4; ++ii) {
            float2 u = unpack2(acc[ii][jj]);
            float t = (u.x + u.y) * sc;
            if (my_sh[ii]  != shj) t = -1e9f;
            if (my_pos[ii] == psj) t = -1e5f;
            p[ii][jj] = t;
        }
    }

    // -------- softmax over 128 keys (16-thread group per i-row) ------------
    float m[4], s[4], inv_s4[4];
#pragma unroll
    for (int ii = 0; ii < 4; ++ii) {
        float mm = p[ii][0];
#pragma unroll
        for (int jj = 1; jj < 8; ++jj) mm = fmaxf(mm, p[ii][jj]);
        m[ii] = mm;
    }
#pragma unroll
    for (int o = 1; o < 16; o <<= 1)
#pragma unroll
        for (int ii = 0; ii < 4; ++ii)
            m[ii] = fmaxf(m[ii], __shfl_xor_sync(0xffffffffu, m[ii], o));
#pragma unroll
    for (int ii = 0; ii < 4; ++ii) {
        float ss2 = 0.f;
#pragma unroll
        for (int jj = 0; jj < 8; ++jj) { p[ii][jj] = expf(p[ii][jj] - m[ii]); ss2 += p[ii][jj]; }
        s[ii] = ss2;
    }
#pragma unroll
    for (int o = 1; o < 16; o <<= 1)
#pragma unroll
        for (int ii = 0; ii < 4; ++ii)
            s[ii] += __shfl_xor_sync(0xffffffffu, s[ii], o);
#pragma unroll
    for (int ii = 0; ii < 4; ++ii) inv_s4[ii] = 1.f / s[ii];
    if (tj == 0) {
#pragma unroll
        for (int ii = 0; ii < 4; ++ii)
            g_lse[brL + (size_t)my_pos[ii]] = m[ii] + logf(s[ii]);
    }

    // -------- stage unnormalized p transposed: p_sT[j][i] -------------------
    __syncthreads();   // all k_s reads done
    float* p_sT = k_s; // 128 rows (j) x KSTR, i contiguous
#pragma unroll
    for (int jj = 0; jj < 8; ++jj)
#pragma unroll
        for (int ii = 0; ii < 4; ++ii)
            p_sT[(tj + 16 * jj) * KSTR + i0 + ii] = p[ii][jj];
    __syncthreads();

    // -------- att = p @ v : i-pairs packed (from p_sT LDS.128), v dup'd -----
    const int d0 = tj * 4;
    unsigned long long accv[2][4];   // [ipair][dd]
#pragma unroll
    for (int e = 0; e < 2; ++e)
#pragma unroll
        for (int dd = 0; dd < 4; ++dd) accv[e][dd] = 0ull;

    const float* pbase = p_sT + i0;        // + j*KSTR
    const float* vbase = v_s + d0;         // + j*KSTR
#pragma unroll 8
    for (int j = 0; j < 128; ++j) {
        ulonglong2 pp = *(const ulonglong2*)(pbase + j * KSTR);  // (p[i0],p[i0+1]),(p[i0+2],p[i0+3])
        float4 vv = *(const float4*)(vbase + j * KSTR);
        unsigned long long vd0 = pack2(vv.x, vv.x);
        unsigned long long vd1 = pack2(vv.y, vv.y);
        unsigned long long vd2 = pack2(vv.z, vv.z);
        unsigned long long vd3 = pack2(vv.w, vv.w);
        accv[0][0] = ffma2(pp.x, vd0, accv[0][0]);
        accv[0][1] = ffma2(pp.x, vd1, accv[0][1]);
        accv[0][2] = ffma2(pp.x, vd2, accv[0][2]);
        accv[0][3] = ffma2(pp.x, vd3, accv[0][3]);
        accv[1][0] = ffma2(pp.y, vd0, accv[1][0]);
        accv[1][1] = ffma2(pp.y, vd1, accv[1][1]);
        accv[1][2] = ffma2(pp.y, vd2, accv[1][2]);
        accv[1][3] = ffma2(pp.y, vd3, accv[1][3]);
    }

    // epilogue: apply 1/s per row, convert to fp16, scatter
#pragma unroll
    for (int e = 0; e < 2; ++e) {
        const unsigned long long isw = pack2(inv_s4[2*e], inv_s4[2*e+1]);
        float2 r[4];
#pragma unroll
        for (int dd = 0; dd < 4; ++dd) r[dd] = unpack2(fmul2(accv[e][dd], isw));
        // row i0+2e   -> r[dd].x ; row i0+2e+1 -> r[dd].y
        {
            __half* orow = g_att + (brL + (size_t)my_pos[2*e]) * D_ + d0;
            __half2 h0 = __floats2half2_rn(r[0].x, r[1].x);
            __half2 h1 = __floats2half2_rn(r[2].x, r[3].x);
            *(__half2*)(orow)     = h0;
            *(__half2*)(orow + 2) = h1;
        }
        {
            __half* orow = g_att + (brL + (size_t)my_pos[2*e+1]) * D_ + d0;
            __half2 h0 = __floats2half2_rn(r[0].y, r[1].y);
            __half2 h1 = __floats2half2_rn(r[2].y, r[3].y);
            *(__half2*)(orow)     = h0;
            *(__half2*)(orow + 2) = h1;
        }
    }
}

// =====================================================================
// K4: per-(b,r) softmax normalizer over L.
// =====================================================================
__global__ void __launch_bounds__(256) lse_reduce_kernel() {
    __shared__ float red[256];
    const int br = blockIdx.x, tid = threadIdx.x;
    const size_t off = (size_t)br * L_;
    float m = -1e30f;
    for (int i = tid; i < L_; i += 256) m = fmaxf(m, g_lse[off + i]);
    red[tid] = m; __syncthreads();
    for (int s2 = 128; s2 > 0; s2 >>= 1) {
        if (tid < s2) red[tid] = fmaxf(red[tid], red[tid + s2]);
        __syncthreads();
    }
    const float mm = red[0];
    __syncthreads();
    float s = 0.f;
    for (int i = tid; i < L_; i += 256) s += expf(g_lse[off + i] - mm);
    red[tid] = s; __syncthreads();
    for (int s2 = 128; s2 > 0; s2 >>= 1) {
        if (tid < s2) red[tid] += red[tid + s2];
        __syncthreads();
    }
    if (tid == 0) { g_m[br] = mm; g_z[br] = red[0]; }
}

// =====================================================================
// K5: out[b,l,d] = sum_r att[b,r,l,d] * exp(lse[b,r,l]-m[b,r]) / z[b,r]
// =====================================================================
__global__ void __launch_bounds__(256) combine_kernel(float* __restrict__ out) {
    const int tid = threadIdx.x;
    const int gl  = blockIdx.x * 4 + (tid >> 6);
    const int d   = tid & 63;
    const int b   = gl >> 13;
    const int l   = gl & (L_ - 1);
    float acc = 0.f;
#pragma unroll
    for (int r = 0; r < 4; ++r) {
        const int br = b * 4 + r;
        const size_t row = (size_t)br * L_ + l;
        const float w = expf(g_lse[row] - g_m[br]) / g_z[br];
        acc = fmaf(__half2float(g_att[row * D_ + d]), w, acc);
    }
    out[(size_t)gl * D_ + d] = acc;
}

// =====================================================================
extern "C" void kernel_launch(void* const* d_in, const int* in_sizes, int n_in,
                              void* d_out, int out_size) {
    const float* q   = (const float*)d_in[0];
    const float* v   = (const float*)d_in[1];
    const float* rmt = (const float*)d_in[2];
    float* out = (float*)d_out;
    (void)in_sizes; (void)n_in; (void)out_size;

    const int att_smem = (128 * KSTR + 128 * KSTR + 128) * (int)sizeof(float)
                       + 256 * (int)sizeof(int);
    cudaFuncSetAttribute(attend_kernel, cudaFuncAttributeMaxDynamicSharedMemorySize, att_smem);

    hash_kernel<<<dim3(L_ / 128, B_), 128>>>(q, rmt);
    sort_kernel<<<B_ * R_, 256>>>();
    attend_kernel<<<B_ * R_ * NB_, 256, att_smem>>>(q, v);
    lse_reduce_kernel<<<B_ * R_, 256>>>();
    combine_kernel<<<B_ * L_ / 4, 256>>>(out);
}

// round 13
// speedup vs baseline: 2.5832x; 1.3952x over previous
#include <cuda_runtime.h>
#include <cuda_fp16.h>
#include <math.h>

#define B_   16
#define L_   8192
#define D_   64
#define R_   4
#define NB_  128     // n_buckets = chunks per (b,r)
#define BL_  64      // bucket length (chunk size)

#define KSTR 68      // hash rm_s stride (floats)
#define KH   72      // k_h / v_h stride in halves (144 B -> ldmatrix conflict-free)
#define OSTR 68      // o_red stride (floats)
#define OHST 72      // o_h stride (halves)

// ---------------- scratch (static device memory; no allocations) ----------------
__device__ __align__(16) __half        g_att[(size_t)B_*R_*L_*D_];   // 67 MB fp16
__device__ __align__(16) float         g_lse[B_*R_*L_];
__device__ __align__(16) int           g_spos[B_*R_*L_];
__device__ __align__(16) unsigned char g_sbkt[B_*R_*L_];
__device__ __align__(16) unsigned char g_bkt[B_*R_*L_];
__device__ float g_m[B_*R_];
__device__ float g_z[B_*R_];

// ---------------- packed f32x2 helpers (hash kernel) ----------------
__device__ __forceinline__ unsigned long long ffma2(unsigned long long a,
                                                    unsigned long long b,
                                                    unsigned long long c) {
    unsigned long long d;
    asm("fma.rn.f32x2 %0, %1, %2, %3;" : "=l"(d) : "l"(a), "l"(b), "l"(c));
    return d;
}
__device__ __forceinline__ unsigned long long pack2(float lo, float hi) {
    unsigned long long r;
    asm("mov.b64 %0, {%1, %2};" : "=l"(r) : "f"(lo), "f"(hi));
    return r;
}
__device__ __forceinline__ float2 unpack2(unsigned long long v) {
    float2 r;
    asm("mov.b64 {%0, %1}, %2;" : "=f"(r.x), "=f"(r.y) : "l"(v));
    return r;
}

// ---------------- tensor-core helpers (attend) ----------------
__device__ __forceinline__ unsigned smaddr(const void* p) {
    return (unsigned)__cvta_generic_to_shared(p);
}
__device__ __forceinline__ void ldsm4(unsigned* d, unsigned a) {
    asm volatile("ldmatrix.sync.aligned.m8n8.x4.shared.b16 {%0,%1,%2,%3}, [%4];"
                 : "=r"(d[0]), "=r"(d[1]), "=r"(d[2]), "=r"(d[3]) : "r"(a));
}
__device__ __forceinline__ void ldsm2(unsigned* d, unsigned a) {
    asm volatile("ldmatrix.sync.aligned.m8n8.x2.shared.b16 {%0,%1}, [%2];"
                 : "=r"(d[0]), "=r"(d[1]) : "r"(a));
}
__device__ __forceinline__ void ldsm4t(unsigned* d, unsigned a) {
    asm volatile("ldmatrix.sync.aligned.m8n8.x4.trans.shared.b16 {%0,%1,%2,%3}, [%4];"
                 : "=r"(d[0]), "=r"(d[1]), "=r"(d[2]), "=r"(d[3]) : "r"(a));
}
__device__ __forceinline__ void mma16816(float* c, const unsigned* a, const unsigned* b) {
    asm volatile("mma.sync.aligned.m16n8k16.row.col.f32.f16.f16.f32 "
                 "{%0,%1,%2,%3}, {%4,%5,%6,%7}, {%8,%9}, {%0,%1,%2,%3};"
                 : "+f"(c[0]), "+f"(c[1]), "+f"(c[2]), "+f"(c[3])
                 : "r"(a[0]), "r"(a[1]), "r"(a[2]), "r"(a[3]), "r"(b[0]), "r"(b[1]));
}
__device__ __forceinline__ unsigned h2u(float lo, float hi) {
    __half2 h = __floats2half2_rn(lo, hi);
    return *(unsigned*)&h;
}

// =====================================================================
// K1: LSH hash (f32x2 path, conflict-free staging). Unchanged from R11.
// =====================================================================
__global__ void __launch_bounds__(128) hash_kernel(const float* __restrict__ q,
                                                   const float* __restrict__ rmat) {
    __shared__ float rm_s[128 * KSTR];
    __shared__ float invc_s[128];
    const int tid = threadIdx.x;
    const int b   = blockIdx.y;
    const int l   = blockIdx.x * 128 + tid;

    float qn[64];
    float ss = 0.f;
    const float4* qrow = (const float4*)(q + ((size_t)b * L_ + l) * D_);
#pragma unroll
    for (int d4 = 0; d4 < 16; ++d4) {
        float4 t = qrow[d4];
        qn[d4*4+0] = t.x; qn[d4*4+1] = t.y; qn[d4*4+2] = t.z; qn[d4*4+3] = t.w;
        ss += t.x*t.x + t.y*t.y + t.z*t.z + t.w*t.w;
    }
    const float inq = 1.f / fmaxf(sqrtf(ss), 1e-12f);
    unsigned long long qn2[32];
#pragma unroll
    for (int d2 = 0; d2 < 32; ++d2) qn2[d2] = pack2(qn[2*d2] * inq, qn[2*d2+1] * inq);

    float bestP[4], bestN[4];
    int   bpi[4],   bni[4];
#pragma unroll
    for (int r = 0; r < 4; ++r) { bestP[r] = -1e30f; bestN[r] = -1e30f; bpi[r] = 0; bni[r] = 0; }

    const float* rm_b = rmat + (size_t)b * D_ * R_ * 64;

#pragma unroll
    for (int half = 0; half < 2; ++half) {
        __syncthreads();
        {
            float s2 = 0.f;
#pragma unroll 16
            for (int k = 0; k < 64; ++k) {
                float x = rm_b[k * 256 + half * 128 + tid];
                rm_s[tid * KSTR + k] = x;
                s2 += x * x;
            }
            invc_s[tid] = 1.f / fmaxf(sqrtf(s2), 1e-12f);
        }
        __syncthreads();
#pragma unroll
        for (int r_loc = 0; r_loc < 2; ++r_loc) {
            const int r = half * 2 + r_loc;
#pragma unroll 2
            for (int n = 0; n < 64; ++n) {
                const int cl = r_loc * 64 + n;
                const ulonglong2* col = (const ulonglong2*)(rm_s + cl * KSTR);
                unsigned long long a0 = 0ull, a1 = 0ull, a2 = 0ull, a3 = 0ull;
#pragma unroll
                for (int d4 = 0; d4 < 16; d4 += 2) {
                    ulonglong2 m0 = col[d4];
                    ulonglong2 m1 = col[d4 + 1];
                    a0 = ffma2(qn2[2*d4+0], m0.x, a0);
                    a1 = ffma2(qn2[2*d4+1], m0.y, a1);
                    a2 = ffma2(qn2[2*d4+2], m1.x, a2);
                    a3 = ffma2(qn2[2*d4+3], m1.y, a3);
                }
                float2 u0 = unpack2(a0), u1 = unpack2(a1), u2 = unpack2(a2), u3 = unpack2(a3);
                float x = (((u0.x + u0.y) + (u1.x + u1.y)) + ((u2.x + u2.y) + (u3.x + u3.y)))
                          * invc_s[cl];
                if ( x > bestP[r]) { bestP[r] =  x; bpi[r] = n; }
                if (-x > bestN[r]) { bestN[r] = -x; bni[r] = n; }
            }
        }
    }
#pragma unroll
    for (int r = 0; r < 4; ++r) {
        int idx = (bestN[r] > bestP[r]) ? (64 + bni[r]) : bpi[r];
        g_bkt[((size_t)(b * R_ + r)) * L_ + l] = (unsigned char)idx;
    }
}

// =====================================================================
// K2: stable counting sort per (b,r).  (unchanged)
// =====================================================================
__global__ void __launch_bounds__(256) sort_kernel() {
    __shared__ unsigned char bkt_s[L_];
    __shared__ int hist[128];
    __shared__ int basec[128];
    __shared__ int warp_hist[8][128];

    const int tid = threadIdx.x;
    const int br  = blockIdx.x;
    const size_t off = (size_t)br * L_;

    {
        const int4* src = (const int4*)(g_bkt + off);
        int4* dst = (int4*)bkt_s;
        for (int i = tid; i < L_ / 16; i += 256) dst[i] = src[i];
    }
    if (tid < 128) hist[tid] = 0;
    __syncthreads();
    for (int i = tid; i < L_; i += 256) atomicAdd(&hist[bkt_s[i]], 1);
    __syncthreads();
    if (tid == 0) {
        int a = 0;
        for (int c = 0; c < 128; ++c) { basec[c] = a; a += hist[c]; }
    }
    __syncthreads();

    const int lane = tid & 31, w = tid >> 5;
    for (int it = 0; it < L_ / 256; ++it) {
        const int idx = it * 256 + tid;
        const int vv  = bkt_s[idx];
        const unsigned mask = __match_any_sync(0xffffffffu, vv);
        const unsigned lt   = (lane == 0) ? 0u : (0xffffffffu >> (32 - lane));
        const int rank = __popc(mask & lt);
        for (int k = lane; k < 128; k += 32) warp_hist[w][k] = 0;
        __syncwarp();
        if ((mask & lt) == 0) warp_hist[w][vv] = __popc(mask);
        __syncthreads();
        int pre = 0;
        for (int ww = 0; ww < w; ++ww) pre += warp_hist[ww][vv];
        const int dest = basec[vv] + pre + rank;
        g_spos[off + dest] = idx;
        g_sbkt[off + dest] = (unsigned char)vv;
        __syncthreads();
        if (tid < 128) {
            int t2 = 0;
#pragma unroll
            for (int ww = 0; ww < 8; ++ww) t2 += warp_hist[ww][tid];
            basec[tid] += t2;
        }
        __syncthreads();
    }
}

// =====================================================================
// K3: lookback attention on TENSOR CORES (mma.sync m16n8k16 fp16->fp32).
//   k_h[128][KH] fp16 gathered q rows (keys 0..127; queries = rows 64..127)
//   v_h[128][KH] fp16 gathered v rows
//   8 warps: w -> (rt = w>>1: row tile of 16 queries, h = w&1: 64-col half)
//   qk: A=ldmatrix(k_h rows 64+..), B=ldmatrix(k_h rows j) [K row-major = B^T]
//   softmax: quad shuffles + cross-half smem combine
//   p: C-fragment repacked in registers as A-fragment (FA2 identity)
//   pv: B=ldmatrix.trans(v_h); cross-half O add + 1/s in smem epilogue.
// =====================================================================
__global__ void __launch_bounds__(256, 2) attend_kernel(const float* __restrict__ q,
                                                        const float* __restrict__ v) {
    extern __shared__ char smraw[];
    __half* k_h    = (__half*)smraw;                    // [128][KH]
    __half* v_h    = k_h + 128 * KH;                    // [128][KH]
    float*  invn_s = (float*)(v_h + 128 * KH);          // 128
    int*    pos_s  = (int*)(invn_s + 128);              // 128
    int*    sh_s   = pos_s + 128;                       // 128
    float*  m_red  = (float*)(sh_s + 128);              // [2][64]
    float*  s_red  = m_red + 128;                       // [2][64]
    float*  o_red  = (float*)k_h;                       // overlay [64][OSTR] (after qk)
    __half* o_h    = (__half*)v_h;                      // overlay [64][OHST] (after pv)

    const int tid   = threadIdx.x;
    const int lane  = tid & 31;
    const int w     = tid >> 5;
    const int rt    = w >> 1;          // query row tile (16 rows)
    const int h     = w & 1;           // column half (64 keys)
    const int bx    = blockIdx.x;
    const int chunk = bx & (NB_ - 1);
    const int br    = bx >> 7;
    const int b     = br >> 2;
    const int prev  = (chunk + NB_ - 1) & (NB_ - 1);
    const size_t brL = (size_t)br * L_;

    // -------- gather 128 rows (prev chunk 0..63, current 64..127) -> fp16 ----
    for (int jr = w; jr < 128; jr += 8) {
        const int slot = (jr < 64) ? prev * BL_ + jr : chunk * BL_ + (jr - 64);
        int pos = 0, bk = 0;
        if (lane == 0) { pos = g_spos[brL + slot]; bk = g_sbkt[brL + slot]; }
        pos = __shfl_sync(0xffffffffu, pos, 0);
        bk  = __shfl_sync(0xffffffffu, bk, 0);
        float ssq = 0.f;
        if (lane < 16) {
            float4 t = *((const float4*)(q + ((size_t)b * L_ + pos) * D_) + lane);
            uint2 pk;
            pk.x = h2u(t.x, t.y);
            pk.y = h2u(t.z, t.w);
            *(uint2*)(k_h + jr * KH + lane * 4) = pk;
            ssq = t.x*t.x + t.y*t.y + t.z*t.z + t.w*t.w;
        } else {
            float4 t = *((const float4*)(v + ((size_t)b * L_ + pos) * D_) + (lane - 16));
            uint2 pk;
            pk.x = h2u(t.x, t.y);
            pk.y = h2u(t.z, t.w);
            *(uint2*)(v_h + jr * KH + (lane - 16) * 4) = pk;
        }
#pragma unroll
        for (int o = 16; o > 0; o >>= 1) ssq += __shfl_xor_sync(0xffffffffu, ssq, o);
        if (lane == 0) {
            invn_s[jr] = 1.f / fmaxf(sqrtf(ssq), 1e-12f);
            pos_s[jr]  = pos;
            sh_s[jr]   = bk;
        }
    }
    __syncthreads();

    // -------- qk MMAs -------------------------------------------------------
    unsigned afr[4][4];
#pragma unroll
    for (int ks = 0; ks < 4; ++ks) {
        unsigned a = smaddr(k_h + (64 + rt * 16 + (lane & 15)) * KH
                                + ks * 16 + ((lane >> 4) & 1) * 8);
        ldsm4(afr[ks], a);
    }
    float cacc[8][4];
#pragma unroll
    for (int ct = 0; ct < 8; ++ct)
#pragma unroll
        for (int e = 0; e < 4; ++e) cacc[ct][e] = 0.f;

#pragma unroll
    for (int ct = 0; ct < 8; ++ct) {
        const int j0 = h * 64 + ct * 8;
#pragma unroll
        for (int ks = 0; ks < 4; ++ks) {
            unsigned bfr[2];
            unsigned a = smaddr(k_h + (j0 + (lane & 7)) * KH
                                    + ks * 16 + ((lane >> 3) & 1) * 8);
            ldsm2(bfr, a);
            mma16816(cacc[ct], afr[ks], bfr);
        }
    }

    // -------- scale + masks -------------------------------------------------
    const int i0 = rt * 16 + (lane >> 2);   // local query row; second row = i0+8
    const int my_sh0  = sh_s[64 + i0],     my_sh1  = sh_s[64 + i0 + 8];
    const int my_pos0 = pos_s[64 + i0],    my_pos1 = pos_s[64 + i0 + 8];
#pragma unroll
    for (int ct = 0; ct < 8; ++ct) {
        const int j = h * 64 + ct * 8 + (lane & 3) * 2;
        const float sc0 = invn_s[j] * 0.125f;
        const float sc1 = invn_s[j + 1] * 0.125f;
        const int shj0 = sh_s[j], shj1 = sh_s[j + 1];
        const int pj0  = pos_s[j], pj1 = pos_s[j + 1];
        float t0 = cacc[ct][0] * sc0;
        float t1 = cacc[ct][1] * sc1;
        float t2 = cacc[ct][2] * sc0;
        float t3 = cacc[ct][3] * sc1;
        if (my_sh0  != shj0) t0 = -1e9f;
        if (my_sh0  != shj1) t1 = -1e9f;
        if (my_sh1  != shj0) t2 = -1e9f;
        if (my_sh1  != shj1) t3 = -1e9f;
        if (my_pos0 == pj0)  t0 = -1e5f;
        if (my_pos0 == pj1)  t1 = -1e5f;
        if (my_pos1 == pj0)  t2 = -1e5f;
        if (my_pos1 == pj1)  t3 = -1e5f;
        cacc[ct][0] = t0; cacc[ct][1] = t1; cacc[ct][2] = t2; cacc[ct][3] = t3;
    }

    // -------- softmax: quad reduce + cross-half combine ---------------------
    float m0 = -1e30f, m1 = -1e30f;
#pragma unroll
    for (int ct = 0; ct < 8; ++ct) {
        m0 = fmaxf(m0, fmaxf(cacc[ct][0], cacc[ct][1]));
        m1 = fmaxf(m1, fmaxf(cacc[ct][2], cacc[ct][3]));
    }
    m0 = fmaxf(m0, __shfl_xor_sync(0xffffffffu, m0, 1));
    m0 = fmaxf(m0, __shfl_xor_sync(0xffffffffu, m0, 2));
    m1 = fmaxf(m1, __shfl_xor_sync(0xffffffffu, m1, 1));
    m1 = fmaxf(m1, __shfl_xor_sync(0xffffffffu, m1, 2));
    if ((lane & 3) == 0) {
        m_red[h * 64 + i0]     = m0;
        m_red[h * 64 + i0 + 8] = m1;
    }
    __syncthreads();
    m0 = fmaxf(m_red[i0],     m_red[64 + i0]);
    m1 = fmaxf(m_red[i0 + 8], m_red[64 + i0 + 8]);

    float s0 = 0.f, s1 = 0.f;
#pragma unroll
    for (int ct = 0; ct < 8; ++ct) {
        cacc[ct][0] = __expf(cacc[ct][0] - m0);
        cacc[ct][1] = __expf(cacc[ct][1] - m0);
        cacc[ct][2] = __expf(cacc[ct][2] - m1);
        cacc[ct][3] = __expf(cacc[ct][3] - m1);
        s0 += cacc[ct][0] + cacc[ct][1];
        s1 += cacc[ct][2] + cacc[ct][3];
    }
    s0 += __shfl_xor_sync(0xffffffffu, s0, 1);
    s0 += __shfl_xor_sync(0xffffffffu, s0, 2);
    s1 += __shfl_xor_sync(0xffffffffu, s1, 1);
    s1 += __shfl_xor_sync(0xffffffffu, s1, 2);
    if ((lane & 3) == 0) {
        s_red[h * 64 + i0]     = s0;
        s_red[h * 64 + i0 + 8] = s1;
    }

    // repack p (unnormalized) into A fragments while the barrier settles
    unsigned pfr[4][4];
#pragma unroll
    for (int kk = 0; kk < 4; ++kk) {
        pfr[kk][0] = h2u(cacc[2*kk][0],   cacc[2*kk][1]);
        pfr[kk][1] = h2u(cacc[2*kk][2],   cacc[2*kk][3]);
        pfr[kk][2] = h2u(cacc[2*kk+1][0], cacc[2*kk+1][1]);
        pfr[kk][3] = h2u(cacc[2*kk+1][2], cacc[2*kk+1][3]);
    }
    __syncthreads();
    s0 = s_red[i0]     + s_red[64 + i0];
    s1 = s_red[i0 + 8] + s_red[64 + i0 + 8];
    const float inv0 = 1.f / s0;
    const float inv1 = 1.f / s1;
    if (h == 0 && (lane & 3) == 0) {
        g_lse[brL + (size_t)my_pos0] = m0 + logf(s0);
        g_lse[brL + (size_t)my_pos1] = m1 + logf(s1);
    }

    // -------- pv MMAs -------------------------------------------------------
    float oacc[8][4];
#pragma unroll
    for (int dt = 0; dt < 8; ++dt)
#pragma unroll
        for (int e = 0; e < 4; ++e) oacc[dt][e] = 0.f;

#pragma unroll
    for (int kk = 0; kk < 4; ++kk) {
        const int j0 = h * 64 + kk * 16;
#pragma unroll
        for (int dt2 = 0; dt2 < 4; ++dt2) {
            unsigned bfr[4];
            unsigned a = smaddr(v_h + (j0 + (lane & 15)) * KH
                                    + dt2 * 16 + ((lane >> 4) & 1) * 8);
            ldsm4t(bfr, a);
            mma16816(oacc[2*dt2],     pfr[kk], bfr);
            mma16816(oacc[2*dt2 + 1], pfr[kk], bfr + 2);
        }
    }

    // -------- cross-half O reduction + normalize + store --------------------
    if (h == 1) {
#pragma unroll
        for (int dt = 0; dt < 8; ++dt) {
            const int d = dt * 8 + (lane & 3) * 2;
            *(float2*)(o_red + i0 * OSTR + d)       = make_float2(oacc[dt][0], oacc[dt][1]);
            *(float2*)(o_red + (i0 + 8) * OSTR + d) = make_float2(oacc[dt][2], oacc[dt][3]);
        }
    }
    __syncthreads();
    if (h == 0) {
#pragma unroll
        for (int dt = 0; dt < 8; ++dt) {
            const int d = dt * 8 + (lane & 3) * 2;
            float2 r0 = *(float2*)(o_red + i0 * OSTR + d);
            float2 r1 = *(float2*)(o_red + (i0 + 8) * OSTR + d);
            *(__half2*)(o_h + i0 * OHST + d) =
                __floats2half2_rn((oacc[dt][0] + r0.x) * inv0, (oacc[dt][1] + r0.y) * inv0);
            *(__half2*)(o_h + (i0 + 8) * OHST + d) =
                __floats2half2_rn((oacc[dt][2] + r1.x) * inv1, (oacc[dt][3] + r1.y) * inv1);
        }
    }
    __syncthreads();

    // coalesced final store: thread (row = tid>>2, seg = tid&3) -> 32B
    {
        const int row = tid >> 2;
        const int seg = tid & 3;
        __half* orow = g_att + (brL + (size_t)pos_s[64 + row]) * D_ + seg * 16;
        uint4 x = *(uint4*)(o_h + row * OHST + seg * 16);
        uint4 y = *(uint4*)(o_h + row * OHST + seg * 16 + 8);
        *(uint4*)(orow)     = x;
        *(uint4*)(orow + 8) = y;
    }
}

// =====================================================================
// K4: per-(b,r) softmax normalizer over L.
// =====================================================================
__global__ void __launch_bounds__(256) lse_reduce_kernel() {
    __shared__ float red[256];
    const int br = blockIdx.x, tid = threadIdx.x;
    const size_t off = (size_t)br * L_;
    float m = -1e30f;
    for (int i = tid; i < L_; i += 256) m = fmaxf(m, g_lse[off + i]);
    red[tid] = m; __syncthreads();
    for (int s2 = 128; s2 > 0; s2 >>= 1) {
        if (tid < s2) red[tid] = fmaxf(red[tid], red[tid + s2]);
        __syncthreads();
    }
    const float mm = red[0];
    __syncthreads();
    float s = 0.f;
    for (int i = tid; i < L_; i += 256) s += expf(g_lse[off + i] - mm);
    red[tid] = s; __syncthreads();
    for (int s2 = 128; s2 > 0; s2 >>= 1) {
        if (tid < s2) red[tid] += red[tid + s2];
        __syncthreads();
    }
    if (tid == 0) { g_m[br] = mm; g_z[br] = red[0]; }
}

// =====================================================================
// K5: out[b,l,d] = sum_r att[b,r,l,d] * exp(lse[b,r,l]-m[b,r]) / z[b,r]
// =====================================================================
__global__ void __launch_bounds__(256) combine_kernel(float* __restrict__ out) {
    const int tid = threadIdx.x;
    const int gl  = blockIdx.x * 4 + (tid >> 6);
    const int d   = tid & 63;
    const int b   = gl >> 13;
    const int l   = gl & (L_ - 1);
    float acc = 0.f;
#pragma unroll
    for (int r = 0; r < 4; ++r) {
        const int br = b * 4 + r;
        const size_t row = (size_t)br * L_ + l;
        const float w = expf(g_lse[row] - g_m[br]) / g_z[br];
        acc = fmaf(__half2float(g_att[row * D_ + d]), w, acc);
    }
    out[(size_t)gl * D_ + d] = acc;
}

// =====================================================================
extern "C" void kernel_launch(void* const* d_in, const int* in_sizes, int n_in,
                              void* d_out, int out_size) {
    const float* q   = (const float*)d_in[0];
    const float* v   = (const float*)d_in[1];
    const float* rmt = (const float*)d_in[2];
    float* out = (float*)d_out;
    (void)in_sizes; (void)n_in; (void)out_size;

    // smem: k_h + v_h (fp16) + invn/pos/sh + m_red + s_red
    const int att_smem = 2 * 128 * KH * (int)sizeof(__half)
                       + 128 * (int)sizeof(float)
                       + 256 * (int)sizeof(int)
                       + 256 * (int)sizeof(float);
    cudaFuncSetAttribute(attend_kernel, cudaFuncAttributeMaxDynamicSharedMemorySize, att_smem);

    hash_kernel<<<dim3(L_ / 128, B_), 128>>>(q, rmt);
    sort_kernel<<<B_ * R_, 256>>>();
    attend_kernel<<<B_ * R_ * NB_, 256, att_smem>>>(q, v);
    lse_reduce_kernel<<<B_ * R_, 256>>>();
    combine_kernel<<<B_ * L_ / 4, 256>>>(out);
}

// round 14
// speedup vs baseline: 2.5917x; 1.0033x over previous
#include <cuda_runtime.h>
#include <cuda_fp16.h>
#include <math.h>

#define B_   16
#define L_   8192
#define D_   64
#define R_   4
#define NB_  128     // n_buckets = chunks per (b,r)
#define BL_  64      // bucket length (chunk size)

#define KSTR 68      // hash rm_s stride (floats)
#define KH   72      // k_h / v_h stride in halves (144 B -> ldmatrix conflict-free)
#define OSTR 68      // o_red stride (floats)
#define OHST 72      // o_h stride (halves)

// ---------------- scratch (static device memory; no allocations) ----------------
__device__ __align__(16) __half        g_att[(size_t)B_*R_*L_*D_];   // 67 MB fp16
__device__ __align__(16) float         g_lse[B_*R_*L_];
__device__ __align__(16) int           g_spos[B_*R_*L_];
__device__ __align__(16) unsigned char g_sbkt[B_*R_*L_];
__device__ __align__(16) unsigned char g_bkt[B_*R_*L_];
__device__ float g_m[B_*R_];
__device__ float g_z[B_*R_];

// ---------------- packed f32x2 helpers (hash kernel) ----------------
__device__ __forceinline__ unsigned long long ffma2(unsigned long long a,
                                                    unsigned long long b,
                                                    unsigned long long c) {
    unsigned long long d;
    asm("fma.rn.f32x2 %0, %1, %2, %3;" : "=l"(d) : "l"(a), "l"(b), "l"(c));
    return d;
}
__device__ __forceinline__ unsigned long long pack2(float lo, float hi) {
    unsigned long long r;
    asm("mov.b64 %0, {%1, %2};" : "=l"(r) : "f"(lo), "f"(hi));
    return r;
}
__device__ __forceinline__ float2 unpack2(unsigned long long v) {
    float2 r;
    asm("mov.b64 {%0, %1}, %2;" : "=f"(r.x), "=f"(r.y) : "l"(v));
    return r;
}

// ---------------- tensor-core helpers (attend) ----------------
__device__ __forceinline__ unsigned smaddr(const void* p) {
    return (unsigned)__cvta_generic_to_shared(p);
}
__device__ __forceinline__ void ldsm4(unsigned* d, unsigned a) {
    asm volatile("ldmatrix.sync.aligned.m8n8.x4.shared.b16 {%0,%1,%2,%3}, [%4];"
                 : "=r"(d[0]), "=r"(d[1]), "=r"(d[2]), "=r"(d[3]) : "r"(a));
}
__device__ __forceinline__ void ldsm2(unsigned* d, unsigned a) {
    asm volatile("ldmatrix.sync.aligned.m8n8.x2.shared.b16 {%0,%1}, [%2];"
                 : "=r"(d[0]), "=r"(d[1]) : "r"(a));
}
__device__ __forceinline__ void ldsm4t(unsigned* d, unsigned a) {
    asm volatile("ldmatrix.sync.aligned.m8n8.x4.trans.shared.b16 {%0,%1,%2,%3}, [%4];"
                 : "=r"(d[0]), "=r"(d[1]), "=r"(d[2]), "=r"(d[3]) : "r"(a));
}
__device__ __forceinline__ void mma16816(float* c, const unsigned* a, const unsigned* b) {
    asm volatile("mma.sync.aligned.m16n8k16.row.col.f32.f16.f16.f32 "
                 "{%0,%1,%2,%3}, {%4,%5,%6,%7}, {%8,%9}, {%0,%1,%2,%3};"
                 : "+f"(c[0]), "+f"(c[1]), "+f"(c[2]), "+f"(c[3])
                 : "r"(a[0]), "r"(a[1]), "r"(a[2]), "r"(a[3]), "r"(b[0]), "r"(b[1]));
}
__device__ __forceinline__ unsigned h2u(float lo, float hi) {
    __half2 h = __floats2half2_rn(lo, hi);
    return *(unsigned*)&h;
}

// =====================================================================
// K1: LSH hash (f32x2 path, conflict-free staging). Unchanged from R11.
// =====================================================================
__global__ void __launch_bounds__(128) hash_kernel(const float* __restrict__ q,
                                                   const float* __restrict__ rmat) {
    __shared__ float rm_s[128 * KSTR];
    __shared__ float invc_s[128];
    const int tid = threadIdx.x;
    const int b   = blockIdx.y;
    const int l   = blockIdx.x * 128 + tid;

    float qn[64];
    float ss = 0.f;
    const float4* qrow = (const float4*)(q + ((size_t)b * L_ + l) * D_);
#pragma unroll
    for (int d4 = 0; d4 < 16; ++d4) {
        float4 t = qrow[d4];
        qn[d4*4+0] = t.x; qn[d4*4+1] = t.y; qn[d4*4+2] = t.z; qn[d4*4+3] = t.w;
        ss += t.x*t.x + t.y*t.y + t.z*t.z + t.w*t.w;
    }
    const float inq = 1.f / fmaxf(sqrtf(ss), 1e-12f);
    unsigned long long qn2[32];
#pragma unroll
    for (int d2 = 0; d2 < 32; ++d2) qn2[d2] = pack2(qn[2*d2] * inq, qn[2*d2+1] * inq);

    float bestP[4], bestN[4];
    int   bpi[4],   bni[4];
#pragma unroll
    for (int r = 0; r < 4; ++r) { bestP[r] = -1e30f; bestN[r] = -1e30f; bpi[r] = 0; bni[r] = 0; }

    const float* rm_b = rmat + (size_t)b * D_ * R_ * 64;

#pragma unroll
    for (int half = 0; half < 2; ++half) {
        __syncthreads();
        {
            float s2 = 0.f;
#pragma unroll 16
            for (int k = 0; k < 64; ++k) {
                float x = rm_b[k * 256 + half * 128 + tid];
                rm_s[tid * KSTR + k] = x;
                s2 += x * x;
            }
            invc_s[tid] = 1.f / fmaxf(sqrtf(s2), 1e-12f);
        }
        __syncthreads();
#pragma unroll
        for (int r_loc = 0; r_loc < 2; ++r_loc) {
            const int r = half * 2 + r_loc;
#pragma unroll 2
            for (int n = 0; n < 64; ++n) {
                const int cl = r_loc * 64 + n;
                const ulonglong2* col = (const ulonglong2*)(rm_s + cl * KSTR);
                unsigned long long a0 = 0ull, a1 = 0ull, a2 = 0ull, a3 = 0ull;
#pragma unroll
                for (int d4 = 0; d4 < 16; d4 += 2) {
                    ulonglong2 m0 = col[d4];
                    ulonglong2 m1 = col[d4 + 1];
                    a0 = ffma2(qn2[2*d4+0], m0.x, a0);
                    a1 = ffma2(qn2[2*d4+1], m0.y, a1);
                    a2 = ffma2(qn2[2*d4+2], m1.x, a2);
                    a3 = ffma2(qn2[2*d4+3], m1.y, a3);
                }
                float2 u0 = unpack2(a0), u1 = unpack2(a1), u2 = unpack2(a2), u3 = unpack2(a3);
                float x = (((u0.x + u0.y) + (u1.x + u1.y)) + ((u2.x + u2.y) + (u3.x + u3.y)))
                          * invc_s[cl];
                if ( x > bestP[r]) { bestP[r] =  x; bpi[r] = n; }
                if (-x > bestN[r]) { bestN[r] = -x; bni[r] = n; }
            }
        }
    }
#pragma unroll
    for (int r = 0; r < 4; ++r) {
        int idx = (bestN[r] > bestP[r]) ? (64 + bni[r]) : bpi[r];
        g_bkt[((size_t)(b * R_ + r)) * L_ + l] = (unsigned char)idx;
    }
}

// =====================================================================
// K2: stable counting sort per (b,r).  (unchanged)
// =====================================================================
__global__ void __launch_bounds__(256) sort_kernel() {
    __shared__ unsigned char bkt_s[L_];
    __shared__ int hist[128];
    __shared__ int basec[128];
    __shared__ int warp_hist[8][128];

    const int tid = threadIdx.x;
    const int br  = blockIdx.x;
    const size_t off = (size_t)br * L_;

    {
        const int4* src = (const int4*)(g_bkt + off);
        int4* dst = (int4*)bkt_s;
        for (int i = tid; i < L_ / 16; i += 256) dst[i] = src[i];
    }
    if (tid < 128) hist[tid] = 0;
    __syncthreads();
    for (int i = tid; i < L_; i += 256) atomicAdd(&hist[bkt_s[i]], 1);
    __syncthreads();
    if (tid == 0) {
        int a = 0;
        for (int c = 0; c < 128; ++c) { basec[c] = a; a += hist[c]; }
    }
    __syncthreads();

    const int lane = tid & 31, w = tid >> 5;
    for (int it = 0; it < L_ / 256; ++it) {
        const int idx = it * 256 + tid;
        const int vv  = bkt_s[idx];
        const unsigned mask = __match_any_sync(0xffffffffu, vv);
        const unsigned lt   = (lane == 0) ? 0u : (0xffffffffu >> (32 - lane));
        const int rank = __popc(mask & lt);
        for (int k = lane; k < 128; k += 32) warp_hist[w][k] = 0;
        __syncwarp();
        if ((mask & lt) == 0) warp_hist[w][vv] = __popc(mask);
        __syncthreads();
        int pre = 0;
        for (int ww = 0; ww < w; ++ww) pre += warp_hist[ww][vv];
        const int dest = basec[vv] + pre + rank;
        g_spos[off + dest] = idx;
        g_sbkt[off + dest] = (unsigned char)vv;
        __syncthreads();
        if (tid < 128) {
            int t2 = 0;
#pragma unroll
            for (int ww = 0; ww < 8; ++ww) t2 += warp_hist[ww][tid];
            basec[tid] += t2;
        }
        __syncthreads();
    }
}

// =====================================================================
// K3: lookback attention on TENSOR CORES (mma.sync m16n8k16 fp16->fp32).
//   k_h[128][KH] fp16 gathered q rows (keys 0..127; queries = rows 64..127)
//   v_h[128][KH] fp16 gathered v rows
//   8 warps: w -> (rt = w>>1: row tile of 16 queries, h = w&1: 64-col half)
//   qk: A=ldmatrix(k_h rows 64+..), B=ldmatrix(k_h rows j) [K row-major = B^T]
//   softmax: quad shuffles + cross-half smem combine
//   p: C-fragment repacked in registers as A-fragment (FA2 identity)
//   pv: B=ldmatrix.trans(v_h); cross-half O add + 1/s in smem epilogue.
// =====================================================================
__global__ void __launch_bounds__(256, 2) attend_kernel(const float* __restrict__ q,
                                                        const float* __restrict__ v) {
    extern __shared__ char smraw[];
    __half* k_h    = (__half*)smraw;                    // [128][KH]
    __half* v_h    = k_h + 128 * KH;                    // [128][KH]
    float*  invn_s = (float*)(v_h + 128 * KH);          // 128
    int*    pos_s  = (int*)(invn_s + 128);              // 128
    int*    sh_s   = pos_s + 128;                       // 128
    float*  m_red  = (float*)(sh_s + 128);              // [2][64]
    float*  s_red  = m_red + 128;                       // [2][64]
    float*  o_red  = (float*)k_h;                       // overlay [64][OSTR] (after qk)
    __half* o_h    = (__half*)v_h;                      // overlay [64][OHST] (after pv)

    const int tid   = threadIdx.x;
    const int lane  = tid & 31;
    const int w     = tid >> 5;
    const int rt    = w >> 1;          // query row tile (16 rows)
    const int h     = w & 1;           // column half (64 keys)
    const int bx    = blockIdx.x;
    const int chunk = bx & (NB_ - 1);
    const int br    = bx >> 7;
    const int b     = br >> 2;
    const int prev  = (chunk + NB_ - 1) & (NB_ - 1);
    const size_t brL = (size_t)br * L_;

    // -------- gather 128 rows (prev chunk 0..63, current 64..127) -> fp16 ----
    for (int jr = w; jr < 128; jr += 8) {
        const int slot = (jr < 64) ? prev * BL_ + jr : chunk * BL_ + (jr - 64);
        int pos = 0, bk = 0;
        if (lane == 0) { pos = g_spos[brL + slot]; bk = g_sbkt[brL + slot]; }
        pos = __shfl_sync(0xffffffffu, pos, 0);
        bk  = __shfl_sync(0xffffffffu, bk, 0);
        float ssq = 0.f;
        if (lane < 16) {
            float4 t = *((const float4*)(q + ((size_t)b * L_ + pos) * D_) + lane);
            uint2 pk;
            pk.x = h2u(t.x, t.y);
            pk.y = h2u(t.z, t.w);
            *(uint2*)(k_h + jr * KH + lane * 4) = pk;
            ssq = t.x*t.x + t.y*t.y + t.z*t.z + t.w*t.w;
        } else {
            float4 t = *((const float4*)(v + ((size_t)b * L_ + pos) * D_) + (lane - 16));
            uint2 pk;
            pk.x = h2u(t.x, t.y);
            pk.y = h2u(t.z, t.w);
            *(uint2*)(v_h + jr * KH + (lane - 16) * 4) = pk;
        }
#pragma unroll
        for (int o = 16; o > 0; o >>= 1) ssq += __shfl_xor_sync(0xffffffffu, ssq, o);
        if (lane == 0) {
            invn_s[jr] = 1.f / fmaxf(sqrtf(ssq), 1e-12f);
            pos_s[jr]  = pos;
            sh_s[jr]   = bk;
        }
    }
    __syncthreads();

    // -------- qk MMAs -------------------------------------------------------
    unsigned afr[4][4];
#pragma unroll
    for (int ks = 0; ks < 4; ++ks) {
        unsigned a = smaddr(k_h + (64 + rt * 16 + (lane & 15)) * KH
                                + ks * 16 + ((lane >> 4) & 1) * 8);
        ldsm4(afr[ks], a);
    }
    float cacc[8][4];
#pragma unroll
    for (int ct = 0; ct < 8; ++ct)
#pragma unroll
        for (int e = 0; e < 4; ++e) cacc[ct][e] = 0.f;

#pragma unroll
    for (int ct = 0; ct < 8; ++ct) {
        const int j0 = h * 64 + ct * 8;
#pragma unroll
        for (int ks = 0; ks < 4; ++ks) {
            unsigned bfr[2];
            unsigned a = smaddr(k_h + (j0 + (lane & 7)) * KH
                                    + ks * 16 + ((lane >> 3) & 1) * 8);
            ldsm2(bfr, a);
            mma16816(cacc[ct], afr[ks], bfr);
        }
    }

    // -------- scale + masks -------------------------------------------------
    const int i0 = rt * 16 + (lane >> 2);   // local query row; second row = i0+8
    const int my_sh0  = sh_s[64 + i0],     my_sh1  = sh_s[64 + i0 + 8];
    const int my_pos0 = pos_s[64 + i0],    my_pos1 = pos_s[64 + i0 + 8];
#pragma unroll
    for (int ct = 0; ct < 8; ++ct) {
        const int j = h * 64 + ct * 8 + (lane & 3) * 2;
        const float sc0 = invn_s[j] * 0.125f;
        const float sc1 = invn_s[j + 1] * 0.125f;
        const int shj0 = sh_s[j], shj1 = sh_s[j + 1];
        const int pj0  = pos_s[j], pj1 = pos_s[j + 1];
        float t0 = cacc[ct][0] * sc0;
        float t1 = cacc[ct][1] * sc1;
        float t2 = cacc[ct][2] * sc0;
        float t3 = cacc[ct][3] * sc1;
        if (my_sh0  != shj0) t0 = -1e9f;
        if (my_sh0  != shj1) t1 = -1e9f;
        if (my_sh1  != shj0) t2 = -1e9f;
        if (my_sh1  != shj1) t3 = -1e9f;
        if (my_pos0 == pj0)  t0 = -1e5f;
        if (my_pos0 == pj1)  t1 = -1e5f;
        if (my_pos1 == pj0)  t2 = -1e5f;
        if (my_pos1 == pj1)  t3 = -1e5f;
        cacc[ct][0] = t0; cacc[ct][1] = t1; cacc[ct][2] = t2; cacc[ct][3] = t3;
    }

    // -------- softmax: quad reduce + cross-half combine ---------------------
    float m0 = -1e30f, m1 = -1e30f;
#pragma unroll
    for (int ct = 0; ct < 8; ++ct) {
        m0 = fmaxf(m0, fmaxf(cacc[ct][0], cacc[ct][1]));
        m1 = fmaxf(m1, fmaxf(cacc[ct][2], cacc[ct][3]));
    }
    m0 = fmaxf(m0, __shfl_xor_sync(0xffffffffu, m0, 1));
    m0 = fmaxf(m0, __shfl_xor_sync(0xffffffffu, m0, 2));
    m1 = fmaxf(m1, __shfl_xor_sync(0xffffffffu, m1, 1));
    m1 = fmaxf(m1, __shfl_xor_sync(0xffffffffu, m1, 2));
    if ((lane & 3) == 0) {
        m_red[h * 64 + i0]     = m0;
        m_red[h * 64 + i0 + 8] = m1;
    }
    __syncthreads();
    m0 = fmaxf(m_red[i0],     m_red[64 + i0]);
    m1 = fmaxf(m_red[i0 + 8], m_red[64 + i0 + 8]);

    float s0 = 0.f, s1 = 0.f;
#pragma unroll
    for (int ct = 0; ct < 8; ++ct) {
        cacc[ct][0] = __expf(cacc[ct][0] - m0);
        cacc[ct][1] = __expf(cacc[ct][1] - m0);
        cacc[ct][2] = __expf(cacc[ct][2] - m1);
        cacc[ct][3] = __expf(cacc[ct][3] - m1);
        s0 += cacc[ct][0] + cacc[ct][1];
        s1 += cacc[ct][2] + cacc[ct][3];
    }
    s0 += __shfl_xor_sync(0xffffffffu, s0, 1);
    s0 += __shfl_xor_sync(0xffffffffu, s0, 2);
    s1 += __shfl_xor_sync(0xffffffffu, s1, 1);
    s1 += __shfl_xor_sync(0xffffffffu, s1, 2);
    if ((lane & 3) == 0) {
        s_red[h * 64 + i0]     = s0;
        s_red[h * 64 + i0 + 8] = s1;
    }

    // repack p (unnormalized) into A fragments while the barrier settles
    unsigned pfr[4][4];
#pragma unroll
    for (int kk = 0; kk < 4; ++kk) {
        pfr[kk][0] = h2u(cacc[2*kk][0],   cacc[2*kk][1]);
        pfr[kk][1] = h2u(cacc[2*kk][2],   cacc[2*kk][3]);
        pfr[kk][2] = h2u(cacc[2*kk+1][0], cacc[2*kk+1][1]);
        pfr[kk][3] = h2u(cacc[2*kk+1][2], cacc[2*kk+1][3]);
    }
    __syncthreads();
    s0 = s_red[i0]     + s_red[64 + i0];
    s1 = s_red[i0 + 8] + s_red[64 + i0 + 8];
    const float inv0 = 1.f / s0;
    const float inv1 = 1.f / s1;
    if (h == 0 && (lane & 3) == 0) {
        g_lse[brL + (size_t)my_pos0] = m0 + logf(s0);
        g_lse[brL + (size_t)my_pos1] = m1 + logf(s1);
    }

    // -------- pv MMAs -------------------------------------------------------
    float oacc[8][4];
#pragma unroll
    for (int dt = 0; dt < 8; ++dt)
#pragma unroll
        for (int e = 0; e < 4; ++e) oacc[dt][e] = 0.f;

#pragma unroll
    for (int kk = 0; kk < 4; ++kk) {
        const int j0 = h * 64 + kk * 16;
#pragma unroll
        for (int dt2 = 0; dt2 < 4; ++dt2) {
            unsigned bfr[4];
            unsigned a = smaddr(v_h + (j0 + (lane & 15)) * KH
                                    + dt2 * 16 + ((lane >> 4) & 1) * 8);
            ldsm4t(bfr, a);
            mma16816(oacc[2*dt2],     pfr[kk], bfr);
            mma16816(oacc[2*dt2 + 1], pfr[kk], bfr + 2);
        }
    }

    // -------- cross-half O reduction + normalize + store --------------------
    if (h == 1) {
#pragma unroll
        for (int dt = 0; dt < 8; ++dt) {
            const int d = dt * 8 + (lane & 3) * 2;
            *(float2*)(o_red + i0 * OSTR + d)       = make_float2(oacc[dt][0], oacc[dt][1]);
            *(float2*)(o_red + (i0 + 8) * OSTR + d) = make_float2(oacc[dt][2], oacc[dt][3]);
        }
    }
    __syncthreads();
    if (h == 0) {
#pragma unroll
        for (int dt = 0; dt < 8; ++dt) {
            const int d = dt * 8 + (lane & 3) * 2;
            float2 r0 = *(float2*)(o_red + i0 * OSTR + d);
            float2 r1 = *(float2*)(o_red + (i0 + 8) * OSTR + d);
            *(__half2*)(o_h + i0 * OHST + d) =
                __floats2half2_rn((oacc[dt][0] + r0.x) * inv0, (oacc[dt][1] + r0.y) * inv0);
            *(__half2*)(o_h + (i0 + 8) * OHST + d) =
                __floats2half2_rn((oacc[dt][2] + r1.x) * inv1, (oacc[dt][3] + r1.y) * inv1);
        }
    }
    __syncthreads();

    // coalesced final store: thread (row = tid>>2, seg = tid&3) -> 32B
    {
        const int row = tid >> 2;
        const int seg = tid & 3;
        __half* orow = g_att + (brL + (size_t)pos_s[64 + row]) * D_ + seg * 16;
        uint4 x = *(uint4*)(o_h + row * OHST + seg * 16);
        uint4 y = *(uint4*)(o_h + row * OHST + seg * 16 + 8);
        *(uint4*)(orow)     = x;
        *(uint4*)(orow + 8) = y;
    }
}

// =====================================================================
// K4: per-(b,r) softmax normalizer over L.
// =====================================================================
__global__ void __launch_bounds__(256) lse_reduce_kernel() {
    __shared__ float red[256];
    const int br = blockIdx.x, tid = threadIdx.x;
    const size_t off = (size_t)br * L_;
    float m = -1e30f;
    for (int i = tid; i < L_; i += 256) m = fmaxf(m, g_lse[off + i]);
    red[tid] = m; __syncthreads();
    for (int s2 = 128; s2 > 0; s2 >>= 1) {
        if (tid < s2) red[tid] = fmaxf(red[tid], red[tid + s2]);
        __syncthreads();
    }
    const float mm = red[0];
    __syncthreads();
    float s = 0.f;
    for (int i = tid; i < L_; i += 256) s += expf(g_lse[off + i] - mm);
    red[tid] = s; __syncthreads();
    for (int s2 = 128; s2 > 0; s2 >>= 1) {
        if (tid < s2) red[tid] += red[tid + s2];
        __syncthreads();
    }
    if (tid == 0) { g_m[br] = mm; g_z[br] = red[0]; }
}

// =====================================================================
// K5: out[b,l,d] = sum_r att[b,r,l,d] * exp(lse[b,r,l]-m[b,r]) / z[b,r]
// =====================================================================
__global__ void __launch_bounds__(256) combine_kernel(float* __restrict__ out) {
    const int tid = threadIdx.x;
    const int gl  = blockIdx.x * 4 + (tid >> 6);
    const int d   = tid & 63;
    const int b   = gl >> 13;
    const int l   = gl & (L_ - 1);
    float acc = 0.f;
#pragma unroll
    for (int r = 0; r < 4; ++r) {
        const int br = b * 4 + r;
        const size_t row = (size_t)br * L_ + l;
        const float w = expf(g_lse[row] - g_m[br]) / g_z[br];
        acc = fmaf(__half2float(g_att[row * D_ + d]), w, acc);
    }
    out[(size_t)gl * D_ + d] = acc;
}

// =====================================================================
extern "C" void kernel_launch(void* const* d_in, const int* in_sizes, int n_in,
                              void* d_out, int out_size) {
    const float* q   = (const float*)d_in[0];
    const float* v   = (const float*)d_in[1];
    const float* rmt = (const float*)d_in[2];
    float* out = (float*)d_out;
    (void)in_sizes; (void)n_in; (void)out_size;

    // smem: k_h + v_h (fp16) + invn/pos/sh + m_red + s_red
    const int att_smem = 2 * 128 * KH * (int)sizeof(__half)
                       + 128 * (int)sizeof(float)
                       + 256 * (int)sizeof(int)
                       + 256 * (int)sizeof(float);
    cudaFuncSetAttribute(attend_kernel, cudaFuncAttributeMaxDynamicSharedMemorySize, att_smem);

    hash_kernel<<<dim3(L_ / 128, B_), 128>>>(q, rmt);
    sort_kernel<<<B_ * R_, 256>>>();
    attend_kernel<<<B_ * R_ * NB_, 256, att_smem>>>(q, v);
    lse_reduce_kernel<<<B_ * R_, 256>>>();
    combine_kernel<<<B_ * L_ / 4, 256>>>(out);
}

// round 15
// speedup vs baseline: 2.5989x; 1.0028x over previous
#include <cuda_runtime.h>
#include <cuda_fp16.h>
#include <math.h>

#define B_   16
#define L_   8192
#define D_   64
#define R_   4
#define NB_  128     // n_buckets = chunks per (b,r)
#define BL_  64      // bucket length (chunk size)

#define KSTR 68      // hash rm_s stride (floats)
#define KH   72      // k_h / v_h stride in halves (144 B -> ldmatrix conflict-free)
#define OSTR 68      // o_red stride (floats)
#define OHST 72      // o_h stride (halves)

// ---------------- scratch (static device memory; no allocations) ----------------
__device__ __align__(16) __half        g_att[(size_t)B_*R_*L_*D_];   // 67 MB fp16
__device__ __align__(16) float         g_lse[B_*R_*L_];
__device__ __align__(16) int           g_spos[B_*R_*L_];
__device__ __align__(16) unsigned char g_sbkt[B_*R_*L_];
__device__ __align__(16) unsigned char g_bkt[B_*R_*L_];
__device__ float g_m[B_*R_];
__device__ float g_z[B_*R_];

// ---------------- packed f32x2 helpers (hash kernel) ----------------
__device__ __forceinline__ unsigned long long ffma2(unsigned long long a,
                                                    unsigned long long b,
                                                    unsigned long long c) {
    unsigned long long d;
    asm("fma.rn.f32x2 %0, %1, %2, %3;" : "=l"(d) : "l"(a), "l"(b), "l"(c));
    return d;
}
__device__ __forceinline__ unsigned long long pack2(float lo, float hi) {
    unsigned long long r;
    asm("mov.b64 %0, {%1, %2};" : "=l"(r) : "f"(lo), "f"(hi));
    return r;
}
__device__ __forceinline__ float2 unpack2(unsigned long long v) {
    float2 r;
    asm("mov.b64 {%0, %1}, %2;" : "=f"(r.x), "=f"(r.y) : "l"(v));
    return r;
}

// ---------------- tensor-core helpers (attend) ----------------
__device__ __forceinline__ unsigned smaddr(const void* p) {
    return (unsigned)__cvta_generic_to_shared(p);
}
__device__ __forceinline__ void ldsm4(unsigned* d, unsigned a) {
    asm volatile("ldmatrix.sync.aligned.m8n8.x4.shared.b16 {%0,%1,%2,%3}, [%4];"
                 : "=r"(d[0]), "=r"(d[1]), "=r"(d[2]), "=r"(d[3]) : "r"(a));
}
__device__ __forceinline__ void ldsm2(unsigned* d, unsigned a) {
    asm volatile("ldmatrix.sync.aligned.m8n8.x2.shared.b16 {%0,%1}, [%2];"
                 : "=r"(d[0]), "=r"(d[1]) : "r"(a));
}
__device__ __forceinline__ void ldsm4t(unsigned* d, unsigned a) {
    asm volatile("ldmatrix.sync.aligned.m8n8.x4.trans.shared.b16 {%0,%1,%2,%3}, [%4];"
                 : "=r"(d[0]), "=r"(d[1]), "=r"(d[2]), "=r"(d[3]) : "r"(a));
}
__device__ __forceinline__ void mma16816(float* c, const unsigned* a, const unsigned* b) {
    asm volatile("mma.sync.aligned.m16n8k16.row.col.f32.f16.f16.f32 "
                 "{%0,%1,%2,%3}, {%4,%5,%6,%7}, {%8,%9}, {%0,%1,%2,%3};"
                 : "+f"(c[0]), "+f"(c[1]), "+f"(c[2]), "+f"(c[3])
                 : "r"(a[0]), "r"(a[1]), "r"(a[2]), "r"(a[3]), "r"(b[0]), "r"(b[1]));
}
__device__ __forceinline__ unsigned h2u(float lo, float hi) {
    __half2 h = __floats2half2_rn(lo, hi);
    return *(unsigned*)&h;
}

// =====================================================================
// K1: LSH hash (f32x2 path, conflict-free staging). Unchanged from R11.
// =====================================================================
__global__ void __launch_bounds__(128) hash_kernel(const float* __restrict__ q,
                                                   const float* __restrict__ rmat) {
    __shared__ float rm_s[128 * KSTR];
    __shared__ float invc_s[128];
    const int tid = threadIdx.x;
    const int b   = blockIdx.y;
    const int l   = blockIdx.x * 128 + tid;

    float qn[64];
    float ss = 0.f;
    const float4* qrow = (const float4*)(q + ((size_t)b * L_ + l) * D_);
#pragma unroll
    for (int d4 = 0; d4 < 16; ++d4) {
        float4 t = qrow[d4];
        qn[d4*4+0] = t.x; qn[d4*4+1] = t.y; qn[d4*4+2] = t.z; qn[d4*4+3] = t.w;
        ss += t.x*t.x + t.y*t.y + t.z*t.z + t.w*t.w;
    }
    const float inq = 1.f / fmaxf(sqrtf(ss), 1e-12f);
    unsigned long long qn2[32];
#pragma unroll
    for (int d2 = 0; d2 < 32; ++d2) qn2[d2] = pack2(qn[2*d2] * inq, qn[2*d2+1] * inq);

    float bestP[4], bestN[4];
    int   bpi[4],   bni[4];
#pragma unroll
    for (int r = 0; r < 4; ++r) { bestP[r] = -1e30f; bestN[r] = -1e30f; bpi[r] = 0; bni[r] = 0; }

    const float* rm_b = rmat + (size_t)b * D_ * R_ * 64;

#pragma unroll
    for (int half = 0; half < 2; ++half) {
        __syncthreads();
        {
            float s2 = 0.f;
#pragma unroll 16
            for (int k = 0; k < 64; ++k) {
                float x = rm_b[k * 256 + half * 128 + tid];
                rm_s[tid * KSTR + k] = x;
                s2 += x * x;
            }
            invc_s[tid] = 1.f / fmaxf(sqrtf(s2), 1e-12f);
        }
        __syncthreads();
#pragma unroll
        for (int r_loc = 0; r_loc < 2; ++r_loc) {
            const int r = half * 2 + r_loc;
#pragma unroll 2
            for (int n = 0; n < 64; ++n) {
                const int cl = r_loc * 64 + n;
                const ulonglong2* col = (const ulonglong2*)(rm_s + cl * KSTR);
                unsigned long long a0 = 0ull, a1 = 0ull, a2 = 0ull, a3 = 0ull;
#pragma unroll
                for (int d4 = 0; d4 < 16; d4 += 2) {
                    ulonglong2 m0 = col[d4];
                    ulonglong2 m1 = col[d4 + 1];
                    a0 = ffma2(qn2[2*d4+0], m0.x, a0);
                    a1 = ffma2(qn2[2*d4+1], m0.y, a1);
                    a2 = ffma2(qn2[2*d4+2], m1.x, a2);
                    a3 = ffma2(qn2[2*d4+3], m1.y, a3);
                }
                float2 u0 = unpack2(a0), u1 = unpack2(a1), u2 = unpack2(a2), u3 = unpack2(a3);
                float x = (((u0.x + u0.y) + (u1.x + u1.y)) + ((u2.x + u2.y) + (u3.x + u3.y)))
                          * invc_s[cl];
                if ( x > bestP[r]) { bestP[r] =  x; bpi[r] = n; }
                if (-x > bestN[r]) { bestN[r] = -x; bni[r] = n; }
            }
        }
    }
#pragma unroll
    for (int r = 0; r < 4; ++r) {
        int idx = (bestN[r] > bestP[r]) ? (64 + bni[r]) : bpi[r];
        g_bkt[((size_t)(b * R_ + r)) * L_ + l] = (unsigned char)idx;
    }
}

// =====================================================================
// K2: stable counting sort per (b,r).  (unchanged)
// =====================================================================
__global__ void __launch_bounds__(256) sort_kernel() {
    __shared__ unsigned char bkt_s[L_];
    __shared__ int hist[128];
    __shared__ int basec[128];
    __shared__ int warp_hist[8][128];

    const int tid = threadIdx.x;
    const int br  = blockIdx.x;
    const size_t off = (size_t)br * L_;

    {
        const int4* src = (const int4*)(g_bkt + off);
        int4* dst = (int4*)bkt_s;
        for (int i = tid; i < L_ / 16; i += 256) dst[i] = src[i];
    }
    if (tid < 128) hist[tid] = 0;
    __syncthreads();
    for (int i = tid; i < L_; i += 256) atomicAdd(&hist[bkt_s[i]], 1);
    __syncthreads();
    if (tid == 0) {
        int a = 0;
        for (int c = 0; c < 128; ++c) { basec[c] = a; a += hist[c]; }
    }
    __syncthreads();

    const int lane = tid & 31, w = tid >> 5;
    for (int it = 0; it < L_ / 256; ++it) {
        const int idx = it * 256 + tid;
        const int vv  = bkt_s[idx];
        const unsigned mask = __match_any_sync(0xffffffffu, vv);
        const unsigned lt   = (lane == 0) ? 0u : (0xffffffffu >> (32 - lane));
        const int rank = __popc(mask & lt);
        for (int k = lane; k < 128; k += 32) warp_hist[w][k] = 0;
        __syncwarp();
        if ((mask & lt) == 0) warp_hist[w][vv] = __popc(mask);
        __syncthreads();
        int pre = 0;
        for (int ww = 0; ww < w; ++ww) pre += warp_hist[ww][vv];
        const int dest = basec[vv] + pre + rank;
        g_spos[off + dest] = idx;
        g_sbkt[off + dest] = (unsigned char)vv;
        __syncthreads();
        if (tid < 128) {
            int t2 = 0;
#pragma unroll
            for (int ww = 0; ww < 8; ++ww) t2 += warp_hist[ww][tid];
            basec[tid] += t2;
        }
        __syncthreads();
    }
}

// =====================================================================
// K3: lookback attention on TENSOR CORES (mma.sync m16n8k16 fp16->fp32).
//   k_h[128][KH] fp16 gathered q rows (keys 0..127; queries = rows 64..127)
//   v_h[128][KH] fp16 gathered v rows
//   8 warps: w -> (rt = w>>1: row tile of 16 queries, h = w&1: 64-col half)
//   qk: A=ldmatrix(k_h rows 64+..), B=ldmatrix(k_h rows j) [K row-major = B^T]
//   softmax: quad shuffles + cross-half smem combine
//   p: C-fragment repacked in registers as A-fragment (FA2 identity)
//   pv: B=ldmatrix.trans(v_h); cross-half O add + 1/s in smem epilogue.
// =====================================================================
__global__ void __launch_bounds__(256, 2) attend_kernel(const float* __restrict__ q,
                                                        const float* __restrict__ v) {
    extern __shared__ char smraw[];
    __half* k_h    = (__half*)smraw;                    // [128][KH]
    __half* v_h    = k_h + 128 * KH;                    // [128][KH]
    float*  invn_s = (float*)(v_h + 128 * KH);          // 128
    int*    pos_s  = (int*)(invn_s + 128);              // 128
    int*    sh_s   = pos_s + 128;                       // 128
    float*  m_red  = (float*)(sh_s + 128);              // [2][64]
    float*  s_red  = m_red + 128;                       // [2][64]
    float*  o_red  = (float*)k_h;                       // overlay [64][OSTR] (after qk)
    __half* o_h    = (__half*)v_h;                      // overlay [64][OHST] (after pv)

    const int tid   = threadIdx.x;
    const int lane  = tid & 31;
    const int w     = tid >> 5;
    const int rt    = w >> 1;          // query row tile (16 rows)
    const int h     = w & 1;           // column half (64 keys)
    const int bx    = blockIdx.x;
    const int chunk = bx & (NB_ - 1);
    const int br    = bx >> 7;
    const int b     = br >> 2;
    const int prev  = (chunk + NB_ - 1) & (NB_ - 1);
    const size_t brL = (size_t)br * L_;

    // -------- gather 128 rows (prev chunk 0..63, current 64..127) -> fp16 ----
    for (int jr = w; jr < 128; jr += 8) {
        const int slot = (jr < 64) ? prev * BL_ + jr : chunk * BL_ + (jr - 64);
        int pos = 0, bk = 0;
        if (lane == 0) { pos = g_spos[brL + slot]; bk = g_sbkt[brL + slot]; }
        pos = __shfl_sync(0xffffffffu, pos, 0);
        bk  = __shfl_sync(0xffffffffu, bk, 0);
        float ssq = 0.f;
        if (lane < 16) {
            float4 t = *((const float4*)(q + ((size_t)b * L_ + pos) * D_) + lane);
            uint2 pk;
            pk.x = h2u(t.x, t.y);
            pk.y = h2u(t.z, t.w);
            *(uint2*)(k_h + jr * KH + lane * 4) = pk;
            ssq = t.x*t.x + t.y*t.y + t.z*t.z + t.w*t.w;
        } else {
            float4 t = *((const float4*)(v + ((size_t)b * L_ + pos) * D_) + (lane - 16));
            uint2 pk;
            pk.x = h2u(t.x, t.y);
            pk.y = h2u(t.z, t.w);
            *(uint2*)(v_h + jr * KH + (lane - 16) * 4) = pk;
        }
#pragma unroll
        for (int o = 16; o > 0; o >>= 1) ssq += __shfl_xor_sync(0xffffffffu, ssq, o);
        if (lane == 0) {
            invn_s[jr] = 1.f / fmaxf(sqrtf(ssq), 1e-12f);
            pos_s[jr]  = pos;
            sh_s[jr]   = bk;
        }
    }
    __syncthreads();

    // -------- qk MMAs -------------------------------------------------------
    unsigned afr[4][4];
#pragma unroll
    for (int ks = 0; ks < 4; ++ks) {
        unsigned a = smaddr(k_h + (64 + rt * 16 + (lane & 15)) * KH
                                + ks * 16 + ((lane >> 4) & 1) * 8);
        ldsm4(afr[ks], a);
    }
    float cacc[8][4];
#pragma unroll
    for (int ct = 0; ct < 8; ++ct)
#pragma unroll
        for (int e = 0; e < 4; ++e) cacc[ct][e] = 0.f;

#pragma unroll
    for (int ct = 0; ct < 8; ++ct) {
        const int j0 = h * 64 + ct * 8;
#pragma unroll
        for (int ks = 0; ks < 4; ++ks) {
            unsigned bfr[2];
            unsigned a = smaddr(k_h + (j0 + (lane & 7)) * KH
                                    + ks * 16 + ((lane >> 3) & 1) * 8);
            ldsm2(bfr, a);
            mma16816(cacc[ct], afr[ks], bfr);
        }
    }

    // -------- scale + masks -------------------------------------------------
    const int i0 = rt * 16 + (lane >> 2);   // local query row; second row = i0+8
    const int my_sh0  = sh_s[64 + i0],     my_sh1  = sh_s[64 + i0 + 8];
    const int my_pos0 = pos_s[64 + i0],    my_pos1 = pos_s[64 + i0 + 8];
#pragma unroll
    for (int ct = 0; ct < 8; ++ct) {
        const int j = h * 64 + ct * 8 + (lane & 3) * 2;
        const float sc0 = invn_s[j] * 0.125f;
        const float sc1 = invn_s[j + 1] * 0.125f;
        const int shj0 = sh_s[j], shj1 = sh_s[j + 1];
        const int pj0  = pos_s[j], pj1 = pos_s[j + 1];
        float t0 = cacc[ct][0] * sc0;
        float t1 = cacc[ct][1] * sc1;
        float t2 = cacc[ct][2] * sc0;
        float t3 = cacc[ct][3] * sc1;
        if (my_sh0  != shj0) t0 = -1e9f;
        if (my_sh0  != shj1) t1 = -1e9f;
        if (my_sh1  != shj0) t2 = -1e9f;
        if (my_sh1  != shj1) t3 = -1e9f;
        if (my_pos0 == pj0)  t0 = -1e5f;
        if (my_pos0 == pj1)  t1 = -1e5f;
        if (my_pos1 == pj0)  t2 = -1e5f;
        if (my_pos1 == pj1)  t3 = -1e5f;
        cacc[ct][0] = t0; cacc[ct][1] = t1; cacc[ct][2] = t2; cacc[ct][3] = t3;
    }

    // -------- softmax: quad reduce + cross-half combine ---------------------
    float m0 = -1e30f, m1 = -1e30f;
#pragma unroll
    for (int ct = 0; ct < 8; ++ct) {
        m0 = fmaxf(m0, fmaxf(cacc[ct][0], cacc[ct][1]));
        m1 = fmaxf(m1, fmaxf(cacc[ct][2], cacc[ct][3]));
    }
    m0 = fmaxf(m0, __shfl_xor_sync(0xffffffffu, m0, 1));
    m0 = fmaxf(m0, __shfl_xor_sync(0xffffffffu, m0, 2));
    m1 = fmaxf(m1, __shfl_xor_sync(0xffffffffu, m1, 1));
    m1 = fmaxf(m1, __shfl_xor_sync(0xffffffffu, m1, 2));
    if ((lane & 3) == 0) {
        m_red[h * 64 + i0]     = m0;
        m_red[h * 64 + i0 + 8] = m1;
    }
    __syncthreads();
    m0 = fmaxf(m_red[i0],     m_red[64 + i0]);
    m1 = fmaxf(m_red[i0 + 8], m_red[64 + i0 + 8]);

    float s0 = 0.f, s1 = 0.f;
#pragma unroll
    for (int ct = 0; ct < 8; ++ct) {
        cacc[ct][0] = __expf(cacc[ct][0] - m0);
        cacc[ct][1] = __expf(cacc[ct][1] - m0);
        cacc[ct][2] = __expf(cacc[ct][2] - m1);
        cacc[ct][3] = __expf(cacc[ct][3] - m1);
        s0 += cacc[ct][0] + cacc[ct][1];
        s1 += cacc[ct][2] + cacc[ct][3];
    }
    s0 += __shfl_xor_sync(0xffffffffu, s0, 1);
    s0 += __shfl_xor_sync(0xffffffffu, s0, 2);
    s1 += __shfl_xor_sync(0xffffffffu, s1, 1);
    s1 += __shfl_xor_sync(0xffffffffu, s1, 2);
    if ((lane & 3) == 0) {
        s_red[h * 64 + i0]     = s0;
        s_red[h * 64 + i0 + 8] = s1;
    }

    // repack p (unnormalized) into A fragments while the barrier settles
    unsigned pfr[4][4];
#pragma unroll
    for (int kk = 0; kk < 4; ++kk) {
        pfr[kk][0] = h2u(cacc[2*kk][0],   cacc[2*kk][1]);
        pfr[kk][1] = h2u(cacc[2*kk][2],   cacc[2*kk][3]);
        pfr[kk][2] = h2u(cacc[2*kk+1][0], cacc[2*kk+1][1]);
        pfr[kk][3] = h2u(cacc[2*kk+1][2], cacc[2*kk+1][3]);
    }
    __syncthreads();
    s0 = s_red[i0]     + s_red[64 + i0];
    s1 = s_red[i0 + 8] + s_red[64 + i0 + 8];
    const float inv0 = 1.f / s0;
    const float inv1 = 1.f / s1;
    if (h == 0 && (lane & 3) == 0) {
        g_lse[brL + (size_t)my_pos0] = m0 + logf(s0);
        g_lse[brL + (size_t)my_pos1] = m1 + logf(s1);
    }

    // -------- pv MMAs -------------------------------------------------------
    float oacc[8][4];
#pragma unroll
    for (int dt = 0; dt < 8; ++dt)
#pragma unroll
        for (int e = 0; e < 4; ++e) oacc[dt][e] = 0.f;

#pragma unroll
    for (int kk = 0; kk < 4; ++kk) {
        const int j0 = h * 64 + kk * 16;
#pragma unroll
        for (int dt2 = 0; dt2 < 4; ++dt2) {
            unsigned bfr[4];
            unsigned a = smaddr(v_h + (j0 + (lane & 15)) * KH
                                    + dt2 * 16 + ((lane >> 4) & 1) * 8);
            ldsm4t(bfr, a);
            mma16816(oacc[2*dt2],     pfr[kk], bfr);
            mma16816(oacc[2*dt2 + 1], pfr[kk], bfr + 2);
        }
    }

    // -------- cross-half O reduction + normalize + store --------------------
    if (h == 1) {
#pragma unroll
        for (int dt = 0; dt < 8; ++dt) {
            const int d = dt * 8 + (lane & 3) * 2;
            *(float2*)(o_red + i0 * OSTR + d)       = make_float2(oacc[dt][0], oacc[dt][1]);
            *(float2*)(o_red + (i0 + 8) * OSTR + d) = make_float2(oacc[dt][2], oacc[dt][3]);
        }
    }
    __syncthreads();
    if (h == 0) {
#pragma unroll
        for (int dt = 0; dt < 8; ++dt) {
            const int d = dt * 8 + (lane & 3) * 2;
            float2 r0 = *(float2*)(o_red + i0 * OSTR + d);
            float2 r1 = *(float2*)(o_red + (i0 + 8) * OSTR + d);
            *(__half2*)(o_h + i0 * OHST + d) =
                __floats2half2_rn((oacc[dt][0] + r0.x) * inv0, (oacc[dt][1] + r0.y) * inv0);
            *(__half2*)(o_h + (i0 + 8) * OHST + d) =
                __floats2half2_rn((oacc[dt][2] + r1.x) * inv1, (oacc[dt][3] + r1.y) * inv1);
        }
    }
    __syncthreads();

    // coalesced final store: thread (row = tid>>2, seg = tid&3) -> 32B
    {
        const int row = tid >> 2;
        const int seg = tid & 3;
        __half* orow = g_att + (brL + (size_t)pos_s[64 + row]) * D_ + seg * 16;
        uint4 x = *(uint4*)(o_h + row * OHST + seg * 16);
        uint4 y = *(uint4*)(o_h + row * OHST + seg * 16 + 8);
        *(uint4*)(orow)     = x;
        *(uint4*)(orow + 8) = y;
    }
}

// =====================================================================
// K4: per-(b,r) softmax normalizer over L.
// =====================================================================
__global__ void __launch_bounds__(256) lse_reduce_kernel() {
    __shared__ float red[256];
    const int br = blockIdx.x, tid = threadIdx.x;
    const size_t off = (size_t)br * L_;
    float m = -1e30f;
    for (int i = tid; i < L_; i += 256) m = fmaxf(m, g_lse[off + i]);
    red[tid] = m; __syncthreads();
    for (int s2 = 128; s2 > 0; s2 >>= 1) {
        if (tid < s2) red[tid] = fmaxf(red[tid], red[tid + s2]);
        __syncthreads();
    }
    const float mm = red[0];
    __syncthreads();
    float s = 0.f;
    for (int i = tid; i < L_; i += 256) s += expf(g_lse[off + i] - mm);
    red[tid] = s; __syncthreads();
    for (int s2 = 128; s2 > 0; s2 >>= 1) {
        if (tid < s2) red[tid] += red[tid + s2];
        __syncthreads();
    }
    if (tid == 0) { g_m[br] = mm; g_z[br] = red[0]; }
}

// =====================================================================
// K5: out[b,l,d] = sum_r att[b,r,l,d] * exp(lse[b,r,l]-m[b,r]) / z[b,r]
// =====================================================================
__global__ void __launch_bounds__(256) combine_kernel(float* __restrict__ out) {
    const int tid = threadIdx.x;
    const int gl  = blockIdx.x * 4 + (tid >> 6);
    const int d   = tid & 63;
    const int b   = gl >> 13;
    const int l   = gl & (L_ - 1);
    float acc = 0.f;
#pragma unroll
    for (int r = 0; r < 4; ++r) {
        const int br = b * 4 + r;
        const size_t row = (size_t)br * L_ + l;
        const float w = expf(g_lse[row] - g_m[br]) / g_z[br];
        acc = fmaf(__half2float(g_att[row * D_ + d]), w, acc);
    }
    out[(size_t)gl * D_ + d] = acc;
}

// =====================================================================
extern "C" void kernel_launch(void* const* d_in, const int* in_sizes, int n_in,
                              void* d_out, int out_size) {
    const float* q   = (const float*)d_in[0];
    const float* v   = (const float*)d_in[1];
    const float* rmt = (const float*)d_in[2];
    float* out = (float*)d_out;
    (void)in_sizes; (void)n_in; (void)out_size;

    // smem: k_h + v_h (fp16) + invn/pos/sh + m_red + s_red
    const int att_smem = 2 * 128 * KH * (int)sizeof(__half)
                       + 128 * (int)sizeof(float)
                       + 256 * (int)sizeof(int)
                       + 256 * (int)sizeof(float);
    cudaFuncSetAttribute(attend_kernel, cudaFuncAttributeMaxDynamicSharedMemorySize, att_smem);

    hash_kernel<<<dim3(L_ / 128, B_), 128>>>(q, rmt);
    sort_kernel<<<B_ * R_, 256>>>();
    attend_kernel<<<B_ * R_ * NB_, 256, att_smem>>>(q, v);
    lse_reduce_kernel<<<B_ * R_, 256>>>();
    combine_kernel<<<B_ * L_ / 4, 256>>>(out);
}